// round 1
// baseline (speedup 1.0000x reference)
#include <cuda_runtime.h>
#include <math.h>

#define P 64
#define NMAX 4096

// ---- persistent device scratch (alloc-free rule) ----
__device__ float g_sq[NMAX];
__device__ float g_D2[(size_t)NMAX * NMAX];      // 64 MB pairwise squared distances
__device__ unsigned int g_maxbits;               // max d2 as ordered uint bits
__device__ float g_rc[3];                        // clamped r0, r1, r2
__device__ float g_S1[NMAX];                     // alpha column sums
__device__ float g_mun[NMAX * P];                // unnormalized mu
__device__ float g_U[NMAX * P];
__device__ float g_bU[NMAX];                     // x_j . U_j
__device__ float g_Un2[NMAX];                    // ||U_j||^2
__device__ float g_S2[NMAX];                     // beta column sums
__device__ float g_accZ[NMAX * P];               // unnormalized e_Z

__device__ __forceinline__ float w1f(float d2, float R2, float R2inv) {
    if (d2 < R2) {
        float b = 1.0f - d2 * R2inv;
        return b * b * b;
    }
    return 0.0f;
}

__device__ __forceinline__ float w2f(float d, float r, float rinv) {
    if (d < 0.5f * r) return 1.0f;
    if (d < r) {
        float t = 2.0f * d * rinv - 1.0f;
        float b = 1.0f - t * t;
        return b * b * b;
    }
    return 0.0f;
}

// ---- K1: row squared norms ----
__global__ void k_sq(const float* __restrict__ x, int n) {
    int w = (blockIdx.x * blockDim.x + threadIdx.x) >> 5;
    int lane = threadIdx.x & 31;
    if (w >= n) return;
    float v0 = x[(size_t)w * P + lane];
    float v1 = x[(size_t)w * P + 32 + lane];
    float s = v0 * v0 + v1 * v1;
    #pragma unroll
    for (int o = 16; o; o >>= 1) s += __shfl_xor_sync(0xffffffffu, s, o);
    if (lane == 0) g_sq[w] = s;
}

// ---- K2: D2 = max(sq_i + sq_j - 2 x x^T, 0), plus global max ----
// 128x128 tile per block, 256 threads, 8x8 microtile. K=64 (full depth, one shot).
__global__ void __launch_bounds__(256) k_gram(const float* __restrict__ x, int n) {
    extern __shared__ float sm[];
    float* As = sm;              // [64][132] k-major
    float* Bs = sm + 64 * 132;   // [64][132] k-major
    const int t = threadIdx.x;
    const int i0 = blockIdx.y * 128;
    const int j0 = blockIdx.x * 128;
    const int c4 = (t & 15) * 4;

    #pragma unroll
    for (int m = 0; m < 8; m++) {
        int row = (t + 256 * m) >> 4;
        float4 a = *(const float4*)&x[(size_t)(i0 + row) * P + c4];
        As[(c4 + 0) * 132 + row] = a.x;
        As[(c4 + 1) * 132 + row] = a.y;
        As[(c4 + 2) * 132 + row] = a.z;
        As[(c4 + 3) * 132 + row] = a.w;
        float4 b = *(const float4*)&x[(size_t)(j0 + row) * P + c4];
        Bs[(c4 + 0) * 132 + row] = b.x;
        Bs[(c4 + 1) * 132 + row] = b.y;
        Bs[(c4 + 2) * 132 + row] = b.z;
        Bs[(c4 + 3) * 132 + row] = b.w;
    }
    __syncthreads();

    const int ty = t >> 4, tx = t & 15;
    float acc[8][8];
    #pragma unroll
    for (int u = 0; u < 8; u++)
        #pragma unroll
        for (int v = 0; v < 8; v++) acc[u][v] = 0.f;

    #pragma unroll 4
    for (int k = 0; k < 64; k++) {
        float4 a0 = *(float4*)&As[k * 132 + ty * 8];
        float4 a1 = *(float4*)&As[k * 132 + ty * 8 + 4];
        float4 b0 = *(float4*)&Bs[k * 132 + tx * 8];
        float4 b1 = *(float4*)&Bs[k * 132 + tx * 8 + 4];
        float av[8] = {a0.x, a0.y, a0.z, a0.w, a1.x, a1.y, a1.z, a1.w};
        float bv[8] = {b0.x, b0.y, b0.z, b0.w, b1.x, b1.y, b1.z, b1.w};
        #pragma unroll
        for (int u = 0; u < 8; u++)
            #pragma unroll
            for (int v = 0; v < 8; v++)
                acc[u][v] += av[u] * bv[v];
    }

    float sqi[8], sqj[8];
    #pragma unroll
    for (int u = 0; u < 8; u++) sqi[u] = g_sq[i0 + ty * 8 + u];
    #pragma unroll
    for (int v = 0; v < 8; v++) sqj[v] = g_sq[j0 + tx * 8 + v];

    __syncthreads();  // done reading As/Bs; reuse sm as [128][132] d2 staging buf

    float lmax = 0.f;
    #pragma unroll
    for (int u = 0; u < 8; u++) {
        #pragma unroll
        for (int v = 0; v < 8; v++) {
            float d = fmaxf(sqi[u] + sqj[v] - 2.f * acc[u][v], 0.f);
            lmax = fmaxf(lmax, d);
            sm[(ty * 8 + u) * 132 + tx * 8 + v] = d;
        }
    }
    #pragma unroll
    for (int o = 16; o; o >>= 1) lmax = fmaxf(lmax, __shfl_xor_sync(0xffffffffu, lmax, o));
    __shared__ float wmax[8];
    if ((t & 31) == 0) wmax[t >> 5] = lmax;
    __syncthreads();  // also publishes d2 staging buf
    if (t == 0) {
        float m = wmax[0];
        #pragma unroll
        for (int i = 1; i < 8; i++) m = fmaxf(m, wmax[i]);
        atomicMax(&g_maxbits, __float_as_uint(m));  // d2 >= 0: uint order == float order
    }

    // coalesced store of the tile
    #pragma unroll
    for (int m = 0; m < 16; m++) {
        int f4 = t + 256 * m;
        int row = f4 >> 5;
        int c = (f4 & 31) * 4;
        float4 v = *(float4*)&sm[row * 132 + c];
        *(float4*)&g_D2[(size_t)(i0 + row) * n + j0 + c] = v;
    }
}

// ---- K3: clamp radii by max distance ----
__global__ void k_scalars(const float* r0, const float* r1, const float* r2) {
    float md = sqrtf(__uint_as_float(g_maxbits));
    g_rc[0] = fminf(*r0, md);
    g_rc[1] = fminf(*r1, md);
    g_rc[2] = fminf(*r2, md);
}

// ---- K4: alpha pass: col sums of w1(D2) and mu_num = W1^T @ x ----
// grid (n/64 j-blocks, 8 i-chunks); 256 threads; 64x64 tiles, 4x4 microtile.
__global__ void __launch_bounds__(256) k_alpha(const float* __restrict__ x, int n) {
    __shared__ float Ws[64 * 68];
    __shared__ float Xs[64 * 68];
    __shared__ float red[16 * 64];
    const int t = threadIdx.x;
    const int j0 = blockIdx.x * 64;
    const int ntiles = (n >> 6) / gridDim.y;
    const int tile0 = blockIdx.y * ntiles;
    const float r0 = g_rc[0];
    const float R2 = r0 * r0;
    const float R2inv = 1.0f / R2;
    const int c4 = (t & 15) * 4;
    const int rb = t >> 4;
    const int ty = t >> 4, tx = t & 15;

    float csum[4] = {0.f, 0.f, 0.f, 0.f};
    float eacc[4][4];
    #pragma unroll
    for (int u = 0; u < 4; u++)
        #pragma unroll
        for (int v = 0; v < 4; v++) eacc[u][v] = 0.f;

    for (int it = 0; it < ntiles; it++) {
        const int i0 = (tile0 + it) * 64;
        __syncthreads();  // previous GEMM reads done before overwrite
        #pragma unroll
        for (int m = 0; m < 4; m++) {
            int row = rb + 16 * m;
            float4 d = *(const float4*)&g_D2[(size_t)(i0 + row) * n + j0 + c4];
            float w0 = w1f(d.x, R2, R2inv);
            float w1 = w1f(d.y, R2, R2inv);
            float w2 = w1f(d.z, R2, R2inv);
            float w3 = w1f(d.w, R2, R2inv);
            csum[0] += w0; csum[1] += w1; csum[2] += w2; csum[3] += w3;
            *(float4*)&Ws[row * 68 + c4] = make_float4(w0, w1, w2, w3);
            *(float4*)&Xs[row * 68 + c4] = *(const float4*)&x[(size_t)(i0 + row) * P + c4];
        }
        __syncthreads();
        #pragma unroll 8
        for (int ii = 0; ii < 64; ii++) {
            float4 a = *(float4*)&Ws[ii * 68 + ty * 4];
            float4 b = *(float4*)&Xs[ii * 68 + tx * 4];
            float av[4] = {a.x, a.y, a.z, a.w};
            float bv[4] = {b.x, b.y, b.z, b.w};
            #pragma unroll
            for (int u = 0; u < 4; u++)
                #pragma unroll
                for (int v = 0; v < 4; v++)
                    eacc[u][v] += av[u] * bv[v];
        }
    }
    __syncthreads();
    *(float4*)&red[rb * 64 + c4] = make_float4(csum[0], csum[1], csum[2], csum[3]);
    __syncthreads();
    if (t < 64) {
        float s = 0.f;
        #pragma unroll
        for (int g = 0; g < 16; g++) s += red[g * 64 + t];
        atomicAdd(&g_S1[j0 + t], s);
    }
    #pragma unroll
    for (int u = 0; u < 4; u++)
        #pragma unroll
        for (int v = 0; v < 4; v++)
            atomicAdd(&g_mun[(size_t)(j0 + ty * 4 + u) * P + tx * 4 + v], eacc[u][v]);
}

// ---- K5: U = x - mu (NaN -> mu=x), b_j = x_j.U_j, ||U_j||^2 ----
__global__ void k_U(const float* __restrict__ x, int n) {
    int w = (blockIdx.x * blockDim.x + threadIdx.x) >> 5;
    int lane = threadIdx.x & 31;
    if (w >= n) return;
    float S1 = g_S1[w];
    float b = 0.f, un2 = 0.f;
    #pragma unroll
    for (int h = 0; h < 2; h++) {
        int p = lane + 32 * h;
        float mu = g_mun[(size_t)w * P + p] / S1;
        float xv = x[(size_t)w * P + p];
        if (isnan(mu)) mu = xv;
        float U = xv - mu;
        g_U[(size_t)w * P + p] = U;
        b += xv * U;
        un2 += U * U;
    }
    #pragma unroll
    for (int o = 16; o; o >>= 1) {
        b += __shfl_xor_sync(0xffffffffu, b, o);
        un2 += __shfl_xor_sync(0xffffffffu, un2, o);
    }
    if (lane == 0) { g_bU[w] = b; g_Un2[w] = un2; }
}

// ---- K6: beta pass (fused): c = x@U^T - b, weights, col sums, acc = W^T @ x ----
__global__ void __launch_bounds__(256) k_beta(const float* __restrict__ x, int n) {
    extern __shared__ float sm[];
    float* Usk = sm;                // [64][68] k-major U for this j-block
    float* Ws  = sm + 64 * 68;      // [64][68] d2 staging -> weights
    float* Xs  = sm + 2 * 64 * 68;  // [64][68] x tile, row-major
    float* red = sm + 3 * 64 * 68;  // [16][64]
    float* bs  = red + 16 * 64;     // [64]
    float* u2s = bs + 64;           // [64]
    const int t = threadIdx.x;
    const int j0 = blockIdx.x * 64;
    const int ntiles = (n >> 6) / gridDim.y;
    const int tile0 = blockIdx.y * ntiles;
    const int c4 = (t & 15) * 4;
    const int rb = t >> 4;
    const int ty = t >> 4, tx = t & 15;
    const float r1 = g_rc[1], r2 = g_rc[2];
    const float r1inv = 1.0f / r1, r2inv = 1.0f / r2;

    #pragma unroll
    for (int m = 0; m < 4; m++) {
        int row = rb + 16 * m;
        float4 u = *(const float4*)&g_U[(size_t)(j0 + row) * P + c4];
        Usk[(c4 + 0) * 68 + row] = u.x;
        Usk[(c4 + 1) * 68 + row] = u.y;
        Usk[(c4 + 2) * 68 + row] = u.z;
        Usk[(c4 + 3) * 68 + row] = u.w;
    }
    if (t < 64) { bs[t] = g_bU[j0 + t]; u2s[t] = g_Un2[j0 + t]; }
    __syncthreads();

    float bv4[4], uv4[4];
    #pragma unroll
    for (int v = 0; v < 4; v++) { bv4[v] = bs[tx * 4 + v]; uv4[v] = u2s[tx * 4 + v]; }

    float eacc[4][4];
    #pragma unroll
    for (int u = 0; u < 4; u++)
        #pragma unroll
        for (int v = 0; v < 4; v++) eacc[u][v] = 0.f;
    float wsum[4] = {0.f, 0.f, 0.f, 0.f};

    for (int it = 0; it < ntiles; it++) {
        const int i0 = (tile0 + it) * 64;
        #pragma unroll
        for (int m = 0; m < 4; m++) {
            int row = rb + 16 * m;
            *(float4*)&Xs[row * 68 + c4] = *(const float4*)&x[(size_t)(i0 + row) * P + c4];
            *(float4*)&Ws[row * 68 + c4] = *(const float4*)&g_D2[(size_t)(i0 + row) * n + j0 + c4];
        }
        __syncthreads();

        // c[i][j] = x_i . U_j
        float cacc[4][4];
        #pragma unroll
        for (int u = 0; u < 4; u++)
            #pragma unroll
            for (int v = 0; v < 4; v++) cacc[u][v] = 0.f;
        #pragma unroll 4
        for (int k = 0; k < 64; k++) {
            float av[4];
            av[0] = Xs[(ty * 4 + 0) * 68 + k];
            av[1] = Xs[(ty * 4 + 1) * 68 + k];
            av[2] = Xs[(ty * 4 + 2) * 68 + k];
            av[3] = Xs[(ty * 4 + 3) * 68 + k];
            float4 b = *(float4*)&Usk[k * 68 + tx * 4];
            float bv[4] = {b.x, b.y, b.z, b.w};
            #pragma unroll
            for (int u = 0; u < 4; u++)
                #pragma unroll
                for (int v = 0; v < 4; v++)
                    cacc[u][v] += av[u] * bv[v];
        }

        // weights (each element owned by one thread: safe in-place Ws overwrite)
        #pragma unroll
        for (int u = 0; u < 4; u++) {
            #pragma unroll
            for (int v = 0; v < 4; v++) {
                int i = ty * 4 + u, j = tx * 4 + v;
                float d2 = Ws[i * 68 + j];
                float c = cacc[u][v] - bv4[v];
                float du2 = fmaxf(c * c * uv4[v], 1e-6f);
                float dvv = sqrtf(fmaxf(d2 - du2, 1e-6f));
                float duu = sqrtf(du2);
                float w = w2f(dvv, r1, r1inv) * w2f(duu, r2, r2inv);
                Ws[i * 68 + j] = w;
                wsum[v] += w;
            }
        }
        __syncthreads();

        // acc[j][p] += sum_i W[i][j] * x[i][p]
        #pragma unroll 8
        for (int ii = 0; ii < 64; ii++) {
            float4 a = *(float4*)&Ws[ii * 68 + ty * 4];
            float4 b = *(float4*)&Xs[ii * 68 + tx * 4];
            float av[4] = {a.x, a.y, a.z, a.w};
            float bvv[4] = {b.x, b.y, b.z, b.w};
            #pragma unroll
            for (int u = 0; u < 4; u++)
                #pragma unroll
                for (int v = 0; v < 4; v++)
                    eacc[u][v] += av[u] * bvv[v];
        }
        __syncthreads();
    }

    *(float4*)&red[ty * 64 + tx * 4] = make_float4(wsum[0], wsum[1], wsum[2], wsum[3]);
    __syncthreads();
    if (t < 64) {
        float s = 0.f;
        #pragma unroll
        for (int g = 0; g < 16; g++) s += red[g * 64 + t];
        atomicAdd(&g_S2[j0 + t], s);
    }
    #pragma unroll
    for (int u = 0; u < 4; u++)
        #pragma unroll
        for (int v = 0; v < 4; v++)
            atomicAdd(&g_accZ[(size_t)(j0 + ty * 4 + u) * P + tx * 4 + v], eacc[u][v]);
}

// ---- K7: e_Z = acc / S2, NaN -> x ----
__global__ void k_out(const float* __restrict__ x, float* __restrict__ out, int n) {
    int idx = blockIdx.x * blockDim.x + threadIdx.x;
    if (idx >= n * P) return;
    int j = idx >> 6;
    float e = g_accZ[idx] / g_S2[j];
    if (isnan(e)) e = x[idx];
    out[idx] = e;
}

extern "C" void kernel_launch(void* const* d_in, const int* in_sizes, int n_in,
                              void* d_out, int out_size) {
    const float* x  = (const float*)d_in[0];
    const float* r0 = (const float*)d_in[1];
    const float* r1 = (const float*)d_in[2];
    const float* r2 = (const float*)d_in[3];
    float* out = (float*)d_out;
    const int n = in_sizes[0] / P;  // 4096

    // zero the accumulators (device globals persist across graph replays)
    void *pMax, *pS1, *pMun, *pS2, *pAcc;
    cudaGetSymbolAddress(&pMax, g_maxbits);
    cudaGetSymbolAddress(&pS1, g_S1);
    cudaGetSymbolAddress(&pMun, g_mun);
    cudaGetSymbolAddress(&pS2, g_S2);
    cudaGetSymbolAddress(&pAcc, g_accZ);
    cudaMemsetAsync(pMax, 0, sizeof(unsigned int));
    cudaMemsetAsync(pS1, 0, (size_t)n * sizeof(float));
    cudaMemsetAsync(pMun, 0, (size_t)n * P * sizeof(float));
    cudaMemsetAsync(pS2, 0, (size_t)n * sizeof(float));
    cudaMemsetAsync(pAcc, 0, (size_t)n * P * sizeof(float));

    k_sq<<<(n + 7) / 8, 256>>>(x, n);

    const int gramSmem = 2 * 64 * 132 * sizeof(float);  // 67584
    cudaFuncSetAttribute(k_gram, cudaFuncAttributeMaxDynamicSharedMemorySize, gramSmem);
    dim3 gGram(n / 128, n / 128);
    k_gram<<<gGram, 256, gramSmem>>>(x, n);

    k_scalars<<<1, 1>>>(r0, r1, r2);

    dim3 gPass(n / 64, 8);
    k_alpha<<<gPass, 256>>>(x, n);

    k_U<<<(n + 7) / 8, 256>>>(x, n);

    const int betaSmem = (3 * 64 * 68 + 16 * 64 + 128) * sizeof(float);  // 56832
    cudaFuncSetAttribute(k_beta, cudaFuncAttributeMaxDynamicSharedMemorySize, betaSmem);
    k_beta<<<gPass, 256, betaSmem>>>(x, n);

    k_out<<<(n * P + 255) / 256, 256>>>(x, out, n);
}

// round 2
// speedup vs baseline: 1.0001x; 1.0001x over previous
#include <cuda_runtime.h>
#include <math.h>

#define P 64
#define NMAX 4096

// ---- persistent device scratch (alloc-free rule) ----
__device__ float g_sq[NMAX];
__device__ float g_D2[(size_t)NMAX * NMAX];      // 64 MB pairwise squared distances
__device__ unsigned int g_maxbits;               // max d2 as ordered uint bits
__device__ float g_rc[3];                        // clamped r0, r1, r2
__device__ float g_S1[NMAX];                     // alpha column sums
__device__ float g_mun[NMAX * P];                // unnormalized mu
__device__ float g_U[NMAX * P];
__device__ float g_bU[NMAX];                     // x_j . U_j
__device__ float g_Un2[NMAX];                    // ||U_j||^2
__device__ float g_S2[NMAX];                     // beta column sums
__device__ float g_accZ[NMAX * P];               // unnormalized e_Z

__device__ __forceinline__ float w1f(float d2, float R2, float R2inv) {
    if (d2 < R2) {
        float b = 1.0f - d2 * R2inv;
        return b * b * b;
    }
    return 0.0f;
}

__device__ __forceinline__ float w2f(float d, float r, float rinv) {
    if (d < 0.5f * r) return 1.0f;
    if (d < r) {
        float t = 2.0f * d * rinv - 1.0f;
        float b = 1.0f - t * t;
        return b * b * b;
    }
    return 0.0f;
}

// ---- K1: row squared norms ----
__global__ void k_sq(const float* __restrict__ x, int n) {
    int w = (blockIdx.x * blockDim.x + threadIdx.x) >> 5;
    int lane = threadIdx.x & 31;
    if (w >= n) return;
    float v0 = x[(size_t)w * P + lane];
    float v1 = x[(size_t)w * P + 32 + lane];
    float s = v0 * v0 + v1 * v1;
    #pragma unroll
    for (int o = 16; o; o >>= 1) s += __shfl_xor_sync(0xffffffffu, s, o);
    if (lane == 0) g_sq[w] = s;
}

// ---- K2: D2 = max(sq_i + sq_j - 2 x x^T, 0), plus global max ----
// 128x128 tile per block, 256 threads, 8x8 microtile. K=64 (full depth, one shot).
__global__ void __launch_bounds__(256) k_gram(const float* __restrict__ x, int n) {
    extern __shared__ float sm[];
    float* As = sm;              // [64][132] k-major
    float* Bs = sm + 64 * 132;   // [64][132] k-major
    const int t = threadIdx.x;
    const int i0 = blockIdx.y * 128;
    const int j0 = blockIdx.x * 128;
    const int c4 = (t & 15) * 4;

    #pragma unroll
    for (int m = 0; m < 8; m++) {
        int row = (t + 256 * m) >> 4;
        float4 a = *(const float4*)&x[(size_t)(i0 + row) * P + c4];
        As[(c4 + 0) * 132 + row] = a.x;
        As[(c4 + 1) * 132 + row] = a.y;
        As[(c4 + 2) * 132 + row] = a.z;
        As[(c4 + 3) * 132 + row] = a.w;
        float4 b = *(const float4*)&x[(size_t)(j0 + row) * P + c4];
        Bs[(c4 + 0) * 132 + row] = b.x;
        Bs[(c4 + 1) * 132 + row] = b.y;
        Bs[(c4 + 2) * 132 + row] = b.z;
        Bs[(c4 + 3) * 132 + row] = b.w;
    }
    __syncthreads();

    const int ty = t >> 4, tx = t & 15;
    float acc[8][8];
    #pragma unroll
    for (int u = 0; u < 8; u++)
        #pragma unroll
        for (int v = 0; v < 8; v++) acc[u][v] = 0.f;

    #pragma unroll 4
    for (int k = 0; k < 64; k++) {
        float4 a0 = *(float4*)&As[k * 132 + ty * 8];
        float4 a1 = *(float4*)&As[k * 132 + ty * 8 + 4];
        float4 b0 = *(float4*)&Bs[k * 132 + tx * 8];
        float4 b1 = *(float4*)&Bs[k * 132 + tx * 8 + 4];
        float av[8] = {a0.x, a0.y, a0.z, a0.w, a1.x, a1.y, a1.z, a1.w};
        float bv[8] = {b0.x, b0.y, b0.z, b0.w, b1.x, b1.y, b1.z, b1.w};
        #pragma unroll
        for (int u = 0; u < 8; u++)
            #pragma unroll
            for (int v = 0; v < 8; v++)
                acc[u][v] += av[u] * bv[v];
    }

    float sqi[8], sqj[8];
    #pragma unroll
    for (int u = 0; u < 8; u++) sqi[u] = g_sq[i0 + ty * 8 + u];
    #pragma unroll
    for (int v = 0; v < 8; v++) sqj[v] = g_sq[j0 + tx * 8 + v];

    __syncthreads();  // done reading As/Bs; reuse sm as [128][132] d2 staging buf

    float lmax = 0.f;
    #pragma unroll
    for (int u = 0; u < 8; u++) {
        #pragma unroll
        for (int v = 0; v < 8; v++) {
            float d = fmaxf(sqi[u] + sqj[v] - 2.f * acc[u][v], 0.f);
            lmax = fmaxf(lmax, d);
            sm[(ty * 8 + u) * 132 + tx * 8 + v] = d;
        }
    }
    #pragma unroll
    for (int o = 16; o; o >>= 1) lmax = fmaxf(lmax, __shfl_xor_sync(0xffffffffu, lmax, o));
    __shared__ float wmax[8];
    if ((t & 31) == 0) wmax[t >> 5] = lmax;
    __syncthreads();  // also publishes d2 staging buf
    if (t == 0) {
        float m = wmax[0];
        #pragma unroll
        for (int i = 1; i < 8; i++) m = fmaxf(m, wmax[i]);
        atomicMax(&g_maxbits, __float_as_uint(m));  // d2 >= 0: uint order == float order
    }

    // coalesced store of the tile
    #pragma unroll
    for (int m = 0; m < 16; m++) {
        int f4 = t + 256 * m;
        int row = f4 >> 5;
        int c = (f4 & 31) * 4;
        float4 v = *(float4*)&sm[row * 132 + c];
        *(float4*)&g_D2[(size_t)(i0 + row) * n + j0 + c] = v;
    }
}

// ---- K3: clamp radii by max distance ----
__global__ void k_scalars(const float* r0, const float* r1, const float* r2) {
    float md = sqrtf(__uint_as_float(g_maxbits));
    g_rc[0] = fminf(*r0, md);
    g_rc[1] = fminf(*r1, md);
    g_rc[2] = fminf(*r2, md);
}

// ---- K4: alpha pass: col sums of w1(D2) and mu_num = W1^T @ x ----
// grid (n/64 j-blocks, 8 i-chunks); 256 threads; 64x64 tiles, 4x4 microtile.
__global__ void __launch_bounds__(256) k_alpha(const float* __restrict__ x, int n) {
    __shared__ float Ws[64 * 68];
    __shared__ float Xs[64 * 68];
    __shared__ float red[16 * 64];
    const int t = threadIdx.x;
    const int j0 = blockIdx.x * 64;
    const int ntiles = (n >> 6) / gridDim.y;
    const int tile0 = blockIdx.y * ntiles;
    const float r0 = g_rc[0];
    const float R2 = r0 * r0;
    const float R2inv = 1.0f / R2;
    const int c4 = (t & 15) * 4;
    const int rb = t >> 4;
    const int ty = t >> 4, tx = t & 15;

    float csum[4] = {0.f, 0.f, 0.f, 0.f};
    float eacc[4][4];
    #pragma unroll
    for (int u = 0; u < 4; u++)
        #pragma unroll
        for (int v = 0; v < 4; v++) eacc[u][v] = 0.f;

    for (int it = 0; it < ntiles; it++) {
        const int i0 = (tile0 + it) * 64;
        __syncthreads();  // previous GEMM reads done before overwrite
        #pragma unroll
        for (int m = 0; m < 4; m++) {
            int row = rb + 16 * m;
            float4 d = *(const float4*)&g_D2[(size_t)(i0 + row) * n + j0 + c4];
            float w0 = w1f(d.x, R2, R2inv);
            float w1 = w1f(d.y, R2, R2inv);
            float w2 = w1f(d.z, R2, R2inv);
            float w3 = w1f(d.w, R2, R2inv);
            csum[0] += w0; csum[1] += w1; csum[2] += w2; csum[3] += w3;
            *(float4*)&Ws[row * 68 + c4] = make_float4(w0, w1, w2, w3);
            *(float4*)&Xs[row * 68 + c4] = *(const float4*)&x[(size_t)(i0 + row) * P + c4];
        }
        __syncthreads();
        #pragma unroll 8
        for (int ii = 0; ii < 64; ii++) {
            float4 a = *(float4*)&Ws[ii * 68 + ty * 4];
            float4 b = *(float4*)&Xs[ii * 68 + tx * 4];
            float av[4] = {a.x, a.y, a.z, a.w};
            float bv[4] = {b.x, b.y, b.z, b.w};
            #pragma unroll
            for (int u = 0; u < 4; u++)
                #pragma unroll
                for (int v = 0; v < 4; v++)
                    eacc[u][v] += av[u] * bv[v];
        }
    }
    __syncthreads();
    *(float4*)&red[rb * 64 + c4] = make_float4(csum[0], csum[1], csum[2], csum[3]);
    __syncthreads();
    if (t < 64) {
        float s = 0.f;
        #pragma unroll
        for (int g = 0; g < 16; g++) s += red[g * 64 + t];
        atomicAdd(&g_S1[j0 + t], s);
    }
    #pragma unroll
    for (int u = 0; u < 4; u++)
        #pragma unroll
        for (int v = 0; v < 4; v++)
            atomicAdd(&g_mun[(size_t)(j0 + ty * 4 + u) * P + tx * 4 + v], eacc[u][v]);
}

// ---- K5: U = x - mu (NaN -> mu=x), b_j = x_j.U_j, ||U_j||^2 ----
__global__ void k_U(const float* __restrict__ x, int n) {
    int w = (blockIdx.x * blockDim.x + threadIdx.x) >> 5;
    int lane = threadIdx.x & 31;
    if (w >= n) return;
    float S1 = g_S1[w];
    float b = 0.f, un2 = 0.f;
    #pragma unroll
    for (int h = 0; h < 2; h++) {
        int p = lane + 32 * h;
        float mu = g_mun[(size_t)w * P + p] / S1;
        float xv = x[(size_t)w * P + p];
        if (isnan(mu)) mu = xv;
        float U = xv - mu;
        g_U[(size_t)w * P + p] = U;
        b += xv * U;
        un2 += U * U;
    }
    #pragma unroll
    for (int o = 16; o; o >>= 1) {
        b += __shfl_xor_sync(0xffffffffu, b, o);
        un2 += __shfl_xor_sync(0xffffffffu, un2, o);
    }
    if (lane == 0) { g_bU[w] = b; g_Un2[w] = un2; }
}

// ---- K6: beta pass (fused): c = x@U^T - b, weights, col sums, acc = W^T @ x ----
__global__ void __launch_bounds__(256) k_beta(const float* __restrict__ x, int n) {
    extern __shared__ float sm[];
    float* Usk = sm;                // [64][68] k-major U for this j-block
    float* Ws  = sm + 64 * 68;      // [64][68] d2 staging -> weights
    float* Xs  = sm + 2 * 64 * 68;  // [64][68] x tile, row-major
    float* red = sm + 3 * 64 * 68;  // [16][64]
    float* bs  = red + 16 * 64;     // [64]
    float* u2s = bs + 64;           // [64]
    const int t = threadIdx.x;
    const int j0 = blockIdx.x * 64;
    const int ntiles = (n >> 6) / gridDim.y;
    const int tile0 = blockIdx.y * ntiles;
    const int c4 = (t & 15) * 4;
    const int rb = t >> 4;
    const int ty = t >> 4, tx = t & 15;
    const float r1 = g_rc[1], r2 = g_rc[2];
    const float r1inv = 1.0f / r1, r2inv = 1.0f / r2;

    #pragma unroll
    for (int m = 0; m < 4; m++) {
        int row = rb + 16 * m;
        float4 u = *(const float4*)&g_U[(size_t)(j0 + row) * P + c4];
        Usk[(c4 + 0) * 68 + row] = u.x;
        Usk[(c4 + 1) * 68 + row] = u.y;
        Usk[(c4 + 2) * 68 + row] = u.z;
        Usk[(c4 + 3) * 68 + row] = u.w;
    }
    if (t < 64) { bs[t] = g_bU[j0 + t]; u2s[t] = g_Un2[j0 + t]; }
    __syncthreads();

    float bv4[4], uv4[4];
    #pragma unroll
    for (int v = 0; v < 4; v++) { bv4[v] = bs[tx * 4 + v]; uv4[v] = u2s[tx * 4 + v]; }

    float eacc[4][4];
    #pragma unroll
    for (int u = 0; u < 4; u++)
        #pragma unroll
        for (int v = 0; v < 4; v++) eacc[u][v] = 0.f;
    float wsum[4] = {0.f, 0.f, 0.f, 0.f};

    for (int it = 0; it < ntiles; it++) {
        const int i0 = (tile0 + it) * 64;
        #pragma unroll
        for (int m = 0; m < 4; m++) {
            int row = rb + 16 * m;
            *(float4*)&Xs[row * 68 + c4] = *(const float4*)&x[(size_t)(i0 + row) * P + c4];
            *(float4*)&Ws[row * 68 + c4] = *(const float4*)&g_D2[(size_t)(i0 + row) * n + j0 + c4];
        }
        __syncthreads();

        // c[i][j] = x_i . U_j
        float cacc[4][4];
        #pragma unroll
        for (int u = 0; u < 4; u++)
            #pragma unroll
            for (int v = 0; v < 4; v++) cacc[u][v] = 0.f;
        #pragma unroll 4
        for (int k = 0; k < 64; k++) {
            float av[4];
            av[0] = Xs[(ty * 4 + 0) * 68 + k];
            av[1] = Xs[(ty * 4 + 1) * 68 + k];
            av[2] = Xs[(ty * 4 + 2) * 68 + k];
            av[3] = Xs[(ty * 4 + 3) * 68 + k];
            float4 b = *(float4*)&Usk[k * 68 + tx * 4];
            float bv[4] = {b.x, b.y, b.z, b.w};
            #pragma unroll
            for (int u = 0; u < 4; u++)
                #pragma unroll
                for (int v = 0; v < 4; v++)
                    cacc[u][v] += av[u] * bv[v];
        }

        // weights (each element owned by one thread: safe in-place Ws overwrite)
        #pragma unroll
        for (int u = 0; u < 4; u++) {
            #pragma unroll
            for (int v = 0; v < 4; v++) {
                int i = ty * 4 + u, j = tx * 4 + v;
                float d2 = Ws[i * 68 + j];
                float c = cacc[u][v] - bv4[v];
                float du2 = fmaxf(c * c * uv4[v], 1e-6f);
                float dvv = sqrtf(fmaxf(d2 - du2, 1e-6f));
                float duu = sqrtf(du2);
                float w = w2f(dvv, r1, r1inv) * w2f(duu, r2, r2inv);
                Ws[i * 68 + j] = w;
                wsum[v] += w;
            }
        }
        __syncthreads();

        // acc[j][p] += sum_i W[i][j] * x[i][p]
        #pragma unroll 8
        for (int ii = 0; ii < 64; ii++) {
            float4 a = *(float4*)&Ws[ii * 68 + ty * 4];
            float4 b = *(float4*)&Xs[ii * 68 + tx * 4];
            float av[4] = {a.x, a.y, a.z, a.w};
            float bvv[4] = {b.x, b.y, b.z, b.w};
            #pragma unroll
            for (int u = 0; u < 4; u++)
                #pragma unroll
                for (int v = 0; v < 4; v++)
                    eacc[u][v] += av[u] * bvv[v];
        }
        __syncthreads();
    }

    *(float4*)&red[ty * 64 + tx * 4] = make_float4(wsum[0], wsum[1], wsum[2], wsum[3]);
    __syncthreads();
    if (t < 64) {
        float s = 0.f;
        #pragma unroll
        for (int g = 0; g < 16; g++) s += red[g * 64 + t];
        atomicAdd(&g_S2[j0 + t], s);
    }
    #pragma unroll
    for (int u = 0; u < 4; u++)
        #pragma unroll
        for (int v = 0; v < 4; v++)
            atomicAdd(&g_accZ[(size_t)(j0 + ty * 4 + u) * P + tx * 4 + v], eacc[u][v]);
}

// ---- K7: e_Z = acc / S2, NaN -> x ----
__global__ void k_out(const float* __restrict__ x, float* __restrict__ out, int n) {
    int idx = blockIdx.x * blockDim.x + threadIdx.x;
    if (idx >= n * P) return;
    int j = idx >> 6;
    float e = g_accZ[idx] / g_S2[j];
    if (isnan(e)) e = x[idx];
    out[idx] = e;
}

extern "C" void kernel_launch(void* const* d_in, const int* in_sizes, int n_in,
                              void* d_out, int out_size) {
    const float* x  = (const float*)d_in[0];
    const float* r0 = (const float*)d_in[1];
    const float* r1 = (const float*)d_in[2];
    const float* r2 = (const float*)d_in[3];
    float* out = (float*)d_out;
    const int n = in_sizes[0] / P;  // 4096

    // zero the accumulators (device globals persist across graph replays)
    void *pMax, *pS1, *pMun, *pS2, *pAcc;
    cudaGetSymbolAddress(&pMax, g_maxbits);
    cudaGetSymbolAddress(&pS1, g_S1);
    cudaGetSymbolAddress(&pMun, g_mun);
    cudaGetSymbolAddress(&pS2, g_S2);
    cudaGetSymbolAddress(&pAcc, g_accZ);
    cudaMemsetAsync(pMax, 0, sizeof(unsigned int));
    cudaMemsetAsync(pS1, 0, (size_t)n * sizeof(float));
    cudaMemsetAsync(pMun, 0, (size_t)n * P * sizeof(float));
    cudaMemsetAsync(pS2, 0, (size_t)n * sizeof(float));
    cudaMemsetAsync(pAcc, 0, (size_t)n * P * sizeof(float));

    k_sq<<<(n + 7) / 8, 256>>>(x, n);

    const int gramSmem = 2 * 64 * 132 * sizeof(float);  // 67584
    cudaFuncSetAttribute(k_gram, cudaFuncAttributeMaxDynamicSharedMemorySize, gramSmem);
    dim3 gGram(n / 128, n / 128);
    k_gram<<<gGram, 256, gramSmem>>>(x, n);

    k_scalars<<<1, 1>>>(r0, r1, r2);

    dim3 gPass(n / 64, 8);
    k_alpha<<<gPass, 256>>>(x, n);

    k_U<<<(n + 7) / 8, 256>>>(x, n);

    const int betaSmem = (3 * 64 * 68 + 16 * 64 + 128) * sizeof(float);  // 56832
    cudaFuncSetAttribute(k_beta, cudaFuncAttributeMaxDynamicSharedMemorySize, betaSmem);
    k_beta<<<gPass, 256, betaSmem>>>(x, n);

    k_out<<<(n * P + 255) / 256, 256>>>(x, out, n);
}

// round 4
// speedup vs baseline: 1.7078x; 1.7076x over previous
#include <cuda_runtime.h>
#include <cuda_fp16.h>
#include <math.h>
#include <stdint.h>

#define P 64
#define NMAX 4096

// ---------------- persistent device scratch ----------------
__device__ float g_sq[NMAX];
__device__ float g_D2[(size_t)NMAX * NMAX];
__device__ unsigned int g_maxbits;
__device__ float g_rc[3];
__device__ float g_S1[NMAX];
__device__ float g_mun[NMAX * P];
__device__ float g_bU[NMAX];
__device__ float g_Un2[NMAX];
__device__ float g_S2[NMAX];
__device__ float g_accZ[NMAX * P];
__device__ __half g_xh[NMAX * P], g_xl[NMAX * P];
__device__ __half g_Uh[NMAX * P], g_Ul[NMAX * P];

// ---------------- helpers ----------------
__device__ __forceinline__ uint32_t su32(const void* p) {
    uint32_t a;
    asm("{ .reg .u64 t; cvta.to.shared.u64 t, %1; cvt.u32.u64 %0, t; }" : "=r"(a) : "l"(p));
    return a;
}
#define SWZ(b) ((uint32_t)(b) ^ ((((uint32_t)(b)) >> 3) & 0x70))

// universal ldmatrix.x4 lane->address map for 128B-row swizzled tiles:
// row = row0 + (lane&7) + ((lane>>3)&1)*8 ; colElem = col0 + (lane>>4)*8  (fp16 elems)
__device__ __forceinline__ uint32_t frag_addr(uint32_t base, int lane, int row0, int col0) {
    int r = row0 + (lane & 7) + ((lane >> 3) & 1) * 8;
    int cb = (col0 + (lane >> 4) * 8) * 2;
    return base + SWZ(r * 128 + cb);
}
__device__ __forceinline__ void ldm_x4(uint32_t* r, uint32_t a) {
    asm volatile("ldmatrix.sync.aligned.m8n8.x4.shared.b16 {%0,%1,%2,%3}, [%4];"
                 : "=r"(r[0]), "=r"(r[1]), "=r"(r[2]), "=r"(r[3]) : "r"(a));
}
__device__ __forceinline__ void ldm_x4t(uint32_t* r, uint32_t a) {
    asm volatile("ldmatrix.sync.aligned.m8n8.x4.trans.shared.b16 {%0,%1,%2,%3}, [%4];"
                 : "=r"(r[0]), "=r"(r[1]), "=r"(r[2]), "=r"(r[3]) : "r"(a));
}
__device__ __forceinline__ void mma16816(float* c, const uint32_t* a, const uint32_t* b) {
    asm volatile(
        "mma.sync.aligned.m16n8k16.row.col.f32.f16.f16.f32 "
        "{%0,%1,%2,%3}, {%4,%5,%6,%7}, {%8,%9}, {%0,%1,%2,%3};"
        : "+f"(c[0]), "+f"(c[1]), "+f"(c[2]), "+f"(c[3])
        : "r"(a[0]), "r"(a[1]), "r"(a[2]), "r"(a[3]), "r"(b[0]), "r"(b[1]));
}
__device__ __forceinline__ uint32_t packh2(float a, float b) {
    __half2 h = __floats2half2_rn(a, b);
    return *(uint32_t*)&h;
}
__device__ __forceinline__ float asqrt(float x) { float r; asm("sqrt.approx.f32 %0,%1;" : "=f"(r) : "f"(x)); return r; }
__device__ __forceinline__ float w1f(float d2, float R2, float R2i) {
    if (d2 < R2) { float b = 1.0f - d2 * R2i; return b * b * b; }
    return 0.0f;
}
__device__ __forceinline__ float w2f(float d, float r, float ri) {
    if (d < 0.5f * r) return 1.0f;
    if (d < r) { float t = 2.0f * d * ri - 1.0f; float b = 1.0f - t * t; return b * b * b; }
    return 0.0f;
}

// ---------------- K: row squared norms ----------------
__global__ void k_sq(const float* __restrict__ x, int n) {
    int w = (blockIdx.x * blockDim.x + threadIdx.x) >> 5;
    int lane = threadIdx.x & 31;
    if (w >= n) return;
    float v0 = x[(size_t)w * P + lane], v1 = x[(size_t)w * P + 32 + lane];
    float s = v0 * v0 + v1 * v1;
    #pragma unroll
    for (int o = 16; o; o >>= 1) s += __shfl_xor_sync(0xffffffffu, s, o);
    if (lane == 0) g_sq[w] = s;
}

// ---------------- K: fp16 hi/lo split of x ----------------
__global__ void k_prep(const float* __restrict__ x, int total4) {
    int idx = blockIdx.x * blockDim.x + threadIdx.x;
    if (idx >= total4) return;
    float4 v = *(const float4*)&x[idx * 4];
    float vv[4] = {v.x, v.y, v.z, v.w};
    float lo[4];
    #pragma unroll
    for (int k = 0; k < 4; k++) {
        __half h = __float2half_rn(vv[k]);
        lo[k] = vv[k] - __half2float(h);
    }
    uint2 ph, pl;
    ph.x = packh2(vv[0], vv[1]); ph.y = packh2(vv[2], vv[3]);
    pl.x = packh2(lo[0], lo[1]); pl.y = packh2(lo[2], lo[3]);
    *(uint2*)&g_xh[idx * 4] = ph;
    *(uint2*)&g_xl[idx * 4] = pl;
}

// ---------------- K: gram -> D2 via HMMA (fp16 x3), 128x128 tile ----------------
// dyn smem: Ah 0 (16K), Al 16384, Bh 32768, Bl 49152, sqi 65536(512), sqj 66048(512)
__global__ void __launch_bounds__(256) k_gram(int n) {
    extern __shared__ char smc[];
    __shared__ float wmax[8];
    uint32_t sb = su32(smc);
    const int t = threadIdx.x, w = t >> 5, lane = t & 31;
    const int i0 = blockIdx.y * 128, j0 = blockIdx.x * 128;
    float* sqi = (float*)(smc + 65536);
    float* sqj = (float*)(smc + 66048);

    for (int q = t; q < 1024; q += 256) {
        int row = q >> 3, cb = (q & 7) * 16;
        uint32_t off = SWZ(row * 128 + cb);
        *(uint4*)(smc + off)         = *(const uint4*)&g_xh[(size_t)(i0 + row) * P + cb / 2];
        *(uint4*)(smc + 16384 + off) = *(const uint4*)&g_xl[(size_t)(i0 + row) * P + cb / 2];
        *(uint4*)(smc + 32768 + off) = *(const uint4*)&g_xh[(size_t)(j0 + row) * P + cb / 2];
        *(uint4*)(smc + 49152 + off) = *(const uint4*)&g_xl[(size_t)(j0 + row) * P + cb / 2];
    }
    if (t < 128) sqi[t] = g_sq[i0 + t];
    else sqj[t - 128] = g_sq[j0 + t - 128];
    __syncthreads();

    const int m0 = (w & 3) * 32, n0w = (w >> 2) * 64;
    float C[2][8][4];
    #pragma unroll
    for (int a = 0; a < 2; a++)
        #pragma unroll
        for (int b = 0; b < 8; b++)
            #pragma unroll
            for (int e = 0; e < 4; e++) C[a][b][e] = 0.f;

    #pragma unroll
    for (int ks = 0; ks < 4; ks++) {
        int k0 = ks * 16;
        uint32_t Ah[2][4], Al[2][4];
        #pragma unroll
        for (int mi = 0; mi < 2; mi++) {
            ldm_x4(Ah[mi], frag_addr(sb,         lane, m0 + mi * 16, k0));
            ldm_x4(Al[mi], frag_addr(sb + 16384, lane, m0 + mi * 16, k0));
        }
        #pragma unroll
        for (int gq = 0; gq < 4; gq++) {
            uint32_t Bh[4], Bl[4];
            ldm_x4(Bh, frag_addr(sb + 32768, lane, n0w + gq * 16, k0));  // non-trans: rows=j(n)
            ldm_x4(Bl, frag_addr(sb + 49152, lane, n0w + gq * 16, k0));
            #pragma unroll
            for (int h = 0; h < 2; h++) {
                int ni = gq * 2 + h;
                uint32_t bh[2] = {Bh[h], Bh[h + 2]};
                uint32_t bl[2] = {Bl[h], Bl[h + 2]};
                #pragma unroll
                for (int mi = 0; mi < 2; mi++) {
                    mma16816(C[mi][ni], Ah[mi], bh);
                    mma16816(C[mi][ni], Ah[mi], bl);
                    mma16816(C[mi][ni], Al[mi], bh);
                }
            }
        }
    }

    const int g = lane >> 2, tg = lane & 3;
    float lmax = 0.f;
    #pragma unroll
    for (int mi = 0; mi < 2; mi++)
        #pragma unroll
        for (int e2 = 0; e2 < 2; e2++) {
            int i = m0 + mi * 16 + g + e2 * 8;
            float si = sqi[i];
            #pragma unroll
            for (int ni = 0; ni < 8; ni++) {
                int j = n0w + ni * 8 + tg * 2;
                float d0 = fmaxf(si + sqj[j]     - 2.f * C[mi][ni][e2 * 2],     0.f);
                float d1 = fmaxf(si + sqj[j + 1] - 2.f * C[mi][ni][e2 * 2 + 1], 0.f);
                lmax = fmaxf(lmax, fmaxf(d0, d1));
                *(float2*)&g_D2[(size_t)(i0 + i) * n + j0 + j] = make_float2(d0, d1);
            }
        }
    #pragma unroll
    for (int o = 16; o; o >>= 1) lmax = fmaxf(lmax, __shfl_xor_sync(0xffffffffu, lmax, o));
    if (lane == 0) wmax[w] = lmax;
    __syncthreads();
    if (t == 0) {
        float m = wmax[0];
        #pragma unroll
        for (int q = 1; q < 8; q++) m = fmaxf(m, wmax[q]);
        atomicMax(&g_maxbits, __float_as_uint(m));
    }
}

__global__ void k_scalars(const float* r0, const float* r1, const float* r2) {
    float md = sqrtf(__uint_as_float(g_maxbits));
    g_rc[0] = fminf(*r0, md);
    g_rc[1] = fminf(*r1, md);
    g_rc[2] = fminf(*r2, md);
}

// ---------------- K: alpha — mu_num = W1 @ x (rows j, K = i), S1 sums ----------------
// dyn smem: Wh 0 (16K), Wl 16384 (16K), xh 32768 (8K), xl 40960 (8K) -> 49152
__global__ void __launch_bounds__(256) k_alpha(int n) {
    extern __shared__ char smc[];
    uint32_t sb = su32(smc);
    const int t = threadIdx.x, w = t >> 5, lane = t & 31;
    const int j0 = blockIdx.x * 128;
    const int ibase0 = blockIdx.y * 512;
    const float r0 = g_rc[0];
    const float R2 = r0 * r0, R2i = 1.0f / R2;

    float C[8][4];
    #pragma unroll
    for (int b = 0; b < 8; b++)
        #pragma unroll
        for (int e = 0; e < 4; e++) C[b][e] = 0.f;

    for (int ch = 0; ch < 8; ch++) {
        int ib = ibase0 + ch * 64;
        if (ch) __syncthreads();
        // x tile [64 i][64 p] hi/lo
        for (int q = t; q < 512; q += 256) {
            int row = q >> 3, cb = (q & 7) * 16;
            uint32_t off = SWZ(row * 128 + cb);
            *(uint4*)(smc + 32768 + off) = *(const uint4*)&g_xh[(size_t)(ib + row) * P + cb / 2];
            *(uint4*)(smc + 40960 + off) = *(const uint4*)&g_xl[(size_t)(ib + row) * P + cb / 2];
        }
        // W gen: thread j = t>>1, i-half = (t&1)*32
        {
            int j = t >> 1, ih = (t & 1) * 32;
            const float* drow = &g_D2[(size_t)(j0 + j) * n + ib + ih];
            float s = 0.f;
            #pragma unroll
            for (int q = 0; q < 8; q++) {
                float4 d = *(const float4*)&drow[q * 4];
                float wv[4] = {w1f(d.x, R2, R2i), w1f(d.y, R2, R2i), w1f(d.z, R2, R2i), w1f(d.w, R2, R2i)};
                s += wv[0] + wv[1] + wv[2] + wv[3];
                float lo[4];
                #pragma unroll
                for (int k = 0; k < 4; k++) lo[k] = wv[k] - __half2float(__float2half_rn(wv[k]));
                uint32_t off = SWZ(j * 128 + ih * 2 + q * 8);
                uint2 hh; hh.x = packh2(wv[0], wv[1]); hh.y = packh2(wv[2], wv[3]);
                uint2 ll; ll.x = packh2(lo[0], lo[1]); ll.y = packh2(lo[2], lo[3]);
                *(uint2*)(smc + off) = hh;
                *(uint2*)(smc + 16384 + off) = ll;
            }
            s += __shfl_xor_sync(0xffffffffu, s, 1);
            if ((t & 1) == 0) atomicAdd(&g_S1[j0 + j], s);
        }
        __syncthreads();
        // MMA: A = W rows (w*16), k=i ; B = x trans (rows k=i, n=p)
        #pragma unroll
        for (int ks = 0; ks < 4; ks++) {
            int k0 = ks * 16;
            uint32_t Awh[4], Awl[4];
            ldm_x4(Awh, frag_addr(sb,         lane, w * 16, k0));
            ldm_x4(Awl, frag_addr(sb + 16384, lane, w * 16, k0));
            #pragma unroll
            for (int gq = 0; gq < 4; gq++) {
                uint32_t Bh[4], Bl[4];
                ldm_x4t(Bh, frag_addr(sb + 32768, lane, k0, gq * 16));
                ldm_x4t(Bl, frag_addr(sb + 40960, lane, k0, gq * 16));
                #pragma unroll
                for (int h = 0; h < 2; h++) {
                    int ni = gq * 2 + h;
                    uint32_t bh[2] = {Bh[h * 2], Bh[h * 2 + 1]};
                    uint32_t bl[2] = {Bl[h * 2], Bl[h * 2 + 1]};
                    mma16816(C[ni], Awh, bh);
                    mma16816(C[ni], Awh, bl);
                    mma16816(C[ni], Awl, bh);
                }
            }
        }
    }
    const int g = lane >> 2, tg = lane & 3;
    #pragma unroll
    for (int ni = 0; ni < 8; ni++)
        #pragma unroll
        for (int e = 0; e < 4; e++) {
            int j = j0 + w * 16 + g + (e >> 1) * 8;
            int p = ni * 8 + tg * 2 + (e & 1);
            atomicAdd(&g_mun[(size_t)j * P + p], C[ni][e]);
        }
}

// ---------------- K: U = x - mu (+ fp16 splits), bU, Un2 ----------------
__global__ void k_U(const float* __restrict__ x, int n) {
    int w = (blockIdx.x * blockDim.x + threadIdx.x) >> 5;
    int lane = threadIdx.x & 31;
    if (w >= n) return;
    float S1 = g_S1[w];
    float b = 0.f, un2 = 0.f;
    #pragma unroll
    for (int h = 0; h < 2; h++) {
        int p = lane + 32 * h;
        float mu = g_mun[(size_t)w * P + p] / S1;
        float xv = x[(size_t)w * P + p];
        if (isnan(mu)) mu = xv;
        float U = xv - mu;
        __half uh = __float2half_rn(U);
        g_Uh[(size_t)w * P + p] = uh;
        g_Ul[(size_t)w * P + p] = __float2half_rn(U - __half2float(uh));
        b += xv * U;
        un2 += U * U;
    }
    #pragma unroll
    for (int o = 16; o; o >>= 1) {
        b += __shfl_xor_sync(0xffffffffu, b, o);
        un2 += __shfl_xor_sync(0xffffffffu, un2, o);
    }
    if (lane == 0) { g_bU[w] = b; g_Un2[w] = un2; }
}

// ---------------- K: beta — c-GEMM + weights + acc-GEMM ----------------
// dyn smem: Wh 0 (16K), Wl 16384, xh 32768 (8K), xl 40960, bU 49152(512), U2 49664(512) -> 50176
__global__ void __launch_bounds__(256) k_beta(int n) {
    extern __shared__ char smc[];
    uint32_t sb = su32(smc);
    float* bUs = (float*)(smc + 49152);
    float* U2s = (float*)(smc + 49664);
    const int t = threadIdx.x, w = t >> 5, lane = t & 31;
    const int j0 = blockIdx.x * 128;
    const int ibase0 = blockIdx.y * 512;
    const float rr1 = g_rc[1], rr2 = g_rc[2];
    const float r1i = 1.0f / rr1, r2i = 1.0f / rr2;
    const int g = lane >> 2, tg = lane & 3;

    // stage U (128 rows) into W buffers, load A frags, then release buffers
    for (int q = t; q < 1024; q += 256) {
        int row = q >> 3, cb = (q & 7) * 16;
        uint32_t off = SWZ(row * 128 + cb);
        *(uint4*)(smc + off)         = *(const uint4*)&g_Uh[(size_t)(j0 + row) * P + cb / 2];
        *(uint4*)(smc + 16384 + off) = *(const uint4*)&g_Ul[(size_t)(j0 + row) * P + cb / 2];
    }
    if (t < 128) { bUs[t] = g_bU[j0 + t]; U2s[t] = g_Un2[j0 + t]; }
    __syncthreads();
    uint32_t AUh[4][4], AUl[4][4];
    #pragma unroll
    for (int ks = 0; ks < 4; ks++) {
        ldm_x4(AUh[ks], frag_addr(sb,         lane, w * 16, ks * 16));
        ldm_x4(AUl[ks], frag_addr(sb + 16384, lane, w * 16, ks * 16));
    }
    __syncthreads();

    float accC[8][4];
    #pragma unroll
    for (int b = 0; b < 8; b++)
        #pragma unroll
        for (int e = 0; e < 4; e++) accC[b][e] = 0.f;

    for (int ch = 0; ch < 8; ch++) {
        int ib = ibase0 + ch * 64;
        if (ch) __syncthreads();
        for (int q = t; q < 512; q += 256) {
            int row = q >> 3, cb = (q & 7) * 16;
            uint32_t off = SWZ(row * 128 + cb);
            *(uint4*)(smc + 32768 + off) = *(const uint4*)&g_xh[(size_t)(ib + row) * P + cb / 2];
            *(uint4*)(smc + 40960 + off) = *(const uint4*)&g_xl[(size_t)(ib + row) * P + cb / 2];
        }
        __syncthreads();
        // c-GEMM: c[j][i] = U_j . x_i ; B = x non-trans (rows n=i, k=p)
        float cC[8][4];
        #pragma unroll
        for (int b = 0; b < 8; b++)
            #pragma unroll
            for (int e = 0; e < 4; e++) cC[b][e] = 0.f;
        #pragma unroll
        for (int ks = 0; ks < 4; ks++) {
            int k0 = ks * 16;
            #pragma unroll
            for (int gq = 0; gq < 4; gq++) {
                uint32_t Bh[4], Bl[4];
                ldm_x4(Bh, frag_addr(sb + 32768, lane, gq * 16, k0));
                ldm_x4(Bl, frag_addr(sb + 40960, lane, gq * 16, k0));
                #pragma unroll
                for (int h = 0; h < 2; h++) {
                    int ni = gq * 2 + h;
                    uint32_t bh[2] = {Bh[h], Bh[h + 2]};
                    uint32_t bl[2] = {Bl[h], Bl[h + 2]};
                    mma16816(cC[ni], AUh[ks], bh);
                    mma16816(cC[ni], AUh[ks], bl);
                    mma16816(cC[ni], AUl[ks], bh);
                }
            }
        }
        // weights from cC + d2 -> Wh/Wl smem, row sums -> g_S2
        #pragma unroll
        for (int e2 = 0; e2 < 2; e2++) {
            int jl = w * 16 + g + e2 * 8;
            float bj = bUs[jl], u2 = U2s[jl];
            float rs = 0.f;
            #pragma unroll
            for (int ni = 0; ni < 8; ni++) {
                int il = ni * 8 + tg * 2;
                float2 d = *(const float2*)&g_D2[(size_t)(j0 + jl) * n + ib + il];
                float wv[2], dd[2] = {d.x, d.y};
                #pragma unroll
                for (int q = 0; q < 2; q++) {
                    float cp = cC[ni][e2 * 2 + q] - bj;
                    float du2 = fmaxf(cp * cp * u2, 1e-6f);
                    float dv = asqrt(fmaxf(dd[q] - du2, 1e-6f));
                    float du = asqrt(du2);
                    wv[q] = w2f(dv, rr1, r1i) * w2f(du, rr2, r2i);
                }
                rs += wv[0] + wv[1];
                float l0 = wv[0] - __half2float(__float2half_rn(wv[0]));
                float l1 = wv[1] - __half2float(__float2half_rn(wv[1]));
                uint32_t off = SWZ(jl * 128 + il * 2);
                *(uint32_t*)(smc + off)         = packh2(wv[0], wv[1]);
                *(uint32_t*)(smc + 16384 + off) = packh2(l0, l1);
            }
            rs += __shfl_xor_sync(0xffffffffu, rs, 1);
            rs += __shfl_xor_sync(0xffffffffu, rs, 2);
            if (tg == 0) atomicAdd(&g_S2[j0 + jl], rs);
        }
        __syncthreads();
        // acc-GEMM: acc[j][p] += W[j][i] x[i][p] ; A = W non-trans, B = x trans
        #pragma unroll
        for (int ks = 0; ks < 4; ks++) {
            int k0 = ks * 16;
            uint32_t Awh[4], Awl[4];
            ldm_x4(Awh, frag_addr(sb,         lane, w * 16, k0));
            ldm_x4(Awl, frag_addr(sb + 16384, lane, w * 16, k0));
            #pragma unroll
            for (int gq = 0; gq < 4; gq++) {
                uint32_t Bh[4], Bl[4];
                ldm_x4t(Bh, frag_addr(sb + 32768, lane, k0, gq * 16));
                ldm_x4t(Bl, frag_addr(sb + 40960, lane, k0, gq * 16));
                #pragma unroll
                for (int h = 0; h < 2; h++) {
                    int ni = gq * 2 + h;
                    uint32_t bh[2] = {Bh[h * 2], Bh[h * 2 + 1]};
                    uint32_t bl[2] = {Bl[h * 2], Bl[h * 2 + 1]};
                    mma16816(accC[ni], Awh, bh);
                    mma16816(accC[ni], Awh, bl);
                    mma16816(accC[ni], Awl, bh);
                }
            }
        }
    }
    #pragma unroll
    for (int ni = 0; ni < 8; ni++)
        #pragma unroll
        for (int e = 0; e < 4; e++) {
            int j = j0 + w * 16 + g + (e >> 1) * 8;
            int p = ni * 8 + tg * 2 + (e & 1);
            atomicAdd(&g_accZ[(size_t)j * P + p], accC[ni][e]);
        }
}

// ---------------- K: output ----------------
__global__ void k_out(const float* __restrict__ x, float* __restrict__ out, int n) {
    int idx = blockIdx.x * blockDim.x + threadIdx.x;
    if (idx >= n * P) return;
    int j = idx >> 6;
    float e = g_accZ[idx] / g_S2[j];
    if (isnan(e)) e = x[idx];
    out[idx] = e;
}

extern "C" void kernel_launch(void* const* d_in, const int* in_sizes, int n_in,
                              void* d_out, int out_size) {
    const float* x  = (const float*)d_in[0];
    const float* r0 = (const float*)d_in[1];
    const float* r1 = (const float*)d_in[2];
    const float* r2 = (const float*)d_in[3];
    float* out = (float*)d_out;
    const int n = in_sizes[0] / P;  // 4096

    void *pMax, *pS1, *pMun, *pS2, *pAcc;
    cudaGetSymbolAddress(&pMax, g_maxbits);
    cudaGetSymbolAddress(&pS1, g_S1);
    cudaGetSymbolAddress(&pMun, g_mun);
    cudaGetSymbolAddress(&pS2, g_S2);
    cudaGetSymbolAddress(&pAcc, g_accZ);
    cudaMemsetAsync(pMax, 0, sizeof(unsigned int));
    cudaMemsetAsync(pS1, 0, (size_t)n * sizeof(float));
    cudaMemsetAsync(pMun, 0, (size_t)n * P * sizeof(float));
    cudaMemsetAsync(pS2, 0, (size_t)n * sizeof(float));
    cudaMemsetAsync(pAcc, 0, (size_t)n * P * sizeof(float));

    k_sq<<<(n + 7) / 8, 256>>>(x, n);
    k_prep<<<(n * P / 4 + 255) / 256, 256>>>(x, n * P / 4);

    cudaFuncSetAttribute(k_gram, cudaFuncAttributeMaxDynamicSharedMemorySize, 66560);
    k_gram<<<dim3(n / 128, n / 128), 256, 66560>>>(n);

    k_scalars<<<1, 1>>>(r0, r1, r2);

    cudaFuncSetAttribute(k_alpha, cudaFuncAttributeMaxDynamicSharedMemorySize, 49152);
    k_alpha<<<dim3(n / 128, 8), 256, 49152>>>(n);

    k_U<<<(n + 7) / 8, 256>>>(x, n);

    cudaFuncSetAttribute(k_beta, cudaFuncAttributeMaxDynamicSharedMemorySize, 50176);
    k_beta<<<dim3(n / 128, 8), 256, 50176>>>(n);

    k_out<<<(n * P + 255) / 256, 256>>>(x, out, n);
}

// round 5
// speedup vs baseline: 1.9548x; 1.1446x over previous
#include <cuda_runtime.h>
#include <cuda_fp16.h>
#include <math.h>
#include <stdint.h>

#define P 64
#define NMAX 4096

// ---------------- persistent device scratch ----------------
__device__ float g_sq[NMAX];
__device__ __half g_D2h[(size_t)NMAX * NMAX];   // 32 MB pairwise squared distances (fp16)
__device__ unsigned int g_maxbits;
__device__ float g_S1[NMAX];
__device__ float g_mun[NMAX * P];
__device__ float g_bU[NMAX];
__device__ float g_sU2[NMAX];                   // sqrt(||U_j||^2)
__device__ float g_S2[NMAX];
__device__ float g_accZ[NMAX * P];
__device__ __half g_xh[NMAX * P], g_xl[NMAX * P];
__device__ __half g_Uh[NMAX * P], g_Ul[NMAX * P];

// ---------------- helpers ----------------
__device__ __forceinline__ uint32_t su32(const void* p) {
    uint32_t a;
    asm("{ .reg .u64 t; cvta.to.shared.u64 t, %1; cvt.u32.u64 %0, t; }" : "=r"(a) : "l"(p));
    return a;
}
#define SWZ(b) ((uint32_t)(b) ^ ((((uint32_t)(b)) >> 3) & 0x70))

// ldmatrix.x4 lane->address map for 128B-row swizzled tiles
__device__ __forceinline__ uint32_t frag_addr(uint32_t base, int lane, int row0, int col0) {
    int r = row0 + (lane & 7) + ((lane >> 3) & 1) * 8;
    int cb = (col0 + (lane >> 4) * 8) * 2;
    return base + SWZ(r * 128 + cb);
}
__device__ __forceinline__ void ldm_x4(uint32_t* r, uint32_t a) {
    asm volatile("ldmatrix.sync.aligned.m8n8.x4.shared.b16 {%0,%1,%2,%3}, [%4];"
                 : "=r"(r[0]), "=r"(r[1]), "=r"(r[2]), "=r"(r[3]) : "r"(a));
}
__device__ __forceinline__ void ldm_x4t(uint32_t* r, uint32_t a) {
    asm volatile("ldmatrix.sync.aligned.m8n8.x4.trans.shared.b16 {%0,%1,%2,%3}, [%4];"
                 : "=r"(r[0]), "=r"(r[1]), "=r"(r[2]), "=r"(r[3]) : "r"(a));
}
__device__ __forceinline__ void mma16816(float* c, const uint32_t* a, const uint32_t* b) {
    asm volatile(
        "mma.sync.aligned.m16n8k16.row.col.f32.f16.f16.f32 "
        "{%0,%1,%2,%3}, {%4,%5,%6,%7}, {%8,%9}, {%0,%1,%2,%3};"
        : "+f"(c[0]), "+f"(c[1]), "+f"(c[2]), "+f"(c[3])
        : "r"(a[0]), "r"(a[1]), "r"(a[2]), "r"(a[3]), "r"(b[0]), "r"(b[1]));
}
__device__ __forceinline__ uint32_t packh2(float a, float b) {
    __half2 h = __floats2half2_rn(a, b);
    return *(uint32_t*)&h;
}
__device__ __forceinline__ float asqrt(float x) { float r; asm("sqrt.approx.f32 %0,%1;" : "=f"(r) : "f"(x)); return r; }
// branchless windows
__device__ __forceinline__ float w1f(float d2, float R2i) {
    float s = fmaxf(fmaf(-d2, R2i, 1.0f), 0.0f);
    return s * s * s;
}
__device__ __forceinline__ float w2f(float d, float a /* = 2/r */) {
    float t = __saturatef(fmaf(d, a, -1.0f));
    float s = fmaf(-t, t, 1.0f);
    return s * s * s;
}

// ---------------- K: row squared norms ----------------
__global__ void k_sq(const float* __restrict__ x, int n) {
    int w = (blockIdx.x * blockDim.x + threadIdx.x) >> 5;
    int lane = threadIdx.x & 31;
    if (w >= n) return;
    float v0 = x[(size_t)w * P + lane], v1 = x[(size_t)w * P + 32 + lane];
    float s = v0 * v0 + v1 * v1;
    #pragma unroll
    for (int o = 16; o; o >>= 1) s += __shfl_xor_sync(0xffffffffu, s, o);
    if (lane == 0) g_sq[w] = s;
}

// ---------------- K: fp16 hi/lo split of x ----------------
__global__ void k_prep(const float* __restrict__ x, int total4) {
    int idx = blockIdx.x * blockDim.x + threadIdx.x;
    if (idx >= total4) return;
    float4 v = *(const float4*)&x[idx * 4];
    float vv[4] = {v.x, v.y, v.z, v.w};
    float lo[4];
    #pragma unroll
    for (int k = 0; k < 4; k++) {
        __half h = __float2half_rn(vv[k]);
        lo[k] = vv[k] - __half2float(h);
    }
    uint2 ph, pl;
    ph.x = packh2(vv[0], vv[1]); ph.y = packh2(vv[2], vv[3]);
    pl.x = packh2(lo[0], lo[1]); pl.y = packh2(lo[2], lo[3]);
    *(uint2*)&g_xh[idx * 4] = ph;
    *(uint2*)&g_xl[idx * 4] = pl;
}

// ---------------- K: gram -> D2h via HMMA (fp16 x3), smem-staged fp16 store ----------------
// dyn smem: Ah 0 (16K), Al 16384, Bh 32768, Bl 49152 (stage reuses 32768..65536),
//           sqi 65536(512), sqj 66048(512)
__global__ void __launch_bounds__(256) k_gram(int n) {
    extern __shared__ char smc[];
    __shared__ float wmax[8];
    uint32_t sb = su32(smc);
    const int t = threadIdx.x, w = t >> 5, lane = t & 31;
    const int i0 = blockIdx.y * 128, j0 = blockIdx.x * 128;
    float* sqi = (float*)(smc + 65536);
    float* sqj = (float*)(smc + 66048);
    char* stage = smc + 32768;

    for (int q = t; q < 1024; q += 256) {
        int row = q >> 3, cb = (q & 7) * 16;
        uint32_t off = SWZ(row * 128 + cb);
        *(uint4*)(smc + off)         = *(const uint4*)&g_xh[(size_t)(i0 + row) * P + cb / 2];
        *(uint4*)(smc + 16384 + off) = *(const uint4*)&g_xl[(size_t)(i0 + row) * P + cb / 2];
        *(uint4*)(smc + 32768 + off) = *(const uint4*)&g_xh[(size_t)(j0 + row) * P + cb / 2];
        *(uint4*)(smc + 49152 + off) = *(const uint4*)&g_xl[(size_t)(j0 + row) * P + cb / 2];
    }
    if (t < 128) sqi[t] = g_sq[i0 + t];
    else sqj[t - 128] = g_sq[j0 + t - 128];
    __syncthreads();

    const int m0 = (w & 3) * 32, n0w = (w >> 2) * 64;
    float C[2][8][4];
    #pragma unroll
    for (int a = 0; a < 2; a++)
        #pragma unroll
        for (int b = 0; b < 8; b++)
            #pragma unroll
            for (int e = 0; e < 4; e++) C[a][b][e] = 0.f;

    #pragma unroll
    for (int ks = 0; ks < 4; ks++) {
        int k0 = ks * 16;
        uint32_t Ah[2][4], Al[2][4];
        #pragma unroll
        for (int mi = 0; mi < 2; mi++) {
            ldm_x4(Ah[mi], frag_addr(sb,         lane, m0 + mi * 16, k0));
            ldm_x4(Al[mi], frag_addr(sb + 16384, lane, m0 + mi * 16, k0));
        }
        #pragma unroll
        for (int gq = 0; gq < 4; gq++) {
            uint32_t Bh[4], Bl[4];
            ldm_x4(Bh, frag_addr(sb + 32768, lane, n0w + gq * 16, k0));
            ldm_x4(Bl, frag_addr(sb + 49152, lane, n0w + gq * 16, k0));
            #pragma unroll
            for (int h = 0; h < 2; h++) {
                int ni = gq * 2 + h;
                uint32_t bh[2] = {Bh[h], Bh[h + 2]};
                uint32_t bl[2] = {Bl[h], Bl[h + 2]};
                #pragma unroll
                for (int mi = 0; mi < 2; mi++) {
                    mma16816(C[mi][ni], Ah[mi], bh);
                    mma16816(C[mi][ni], Ah[mi], bl);
                    mma16816(C[mi][ni], Al[mi], bh);
                }
            }
        }
    }
    __syncthreads();  // all ldmatrix reads of B tiles done -> reuse as fp16 stage

    const int g = lane >> 2, tg = lane & 3;
    float lmax = 0.f;
    #pragma unroll
    for (int mi = 0; mi < 2; mi++)
        #pragma unroll
        for (int e2 = 0; e2 < 2; e2++) {
            int i = m0 + mi * 16 + g + e2 * 8;
            float si = sqi[i];
            #pragma unroll
            for (int ni = 0; ni < 8; ni++) {
                int j = n0w + ni * 8 + tg * 2;
                float d0 = fmaxf(si + sqj[j]     - 2.f * C[mi][ni][e2 * 2],     0.f);
                float d1 = fmaxf(si + sqj[j + 1] - 2.f * C[mi][ni][e2 * 2 + 1], 0.f);
                lmax = fmaxf(lmax, fmaxf(d0, d1));
                // swizzled smem stage: conflict-free half2 write
                *(uint32_t*)(stage + i * 256 + ((j * 2) ^ ((i & 7) << 4))) = packh2(d0, d1);
            }
        }
    #pragma unroll
    for (int o = 16; o; o >>= 1) lmax = fmaxf(lmax, __shfl_xor_sync(0xffffffffu, lmax, o));
    if (lane == 0) wmax[w] = lmax;
    __syncthreads();
    if (t == 0) {
        float m = wmax[0];
        #pragma unroll
        for (int q = 1; q < 8; q++) m = fmaxf(m, wmax[q]);
        atomicMax(&g_maxbits, __float_as_uint(m));
    }
    // coalesced fp16 store
    #pragma unroll
    for (int m = 0; m < 8; m++) {
        int fi = t + 256 * m;
        int row = fi >> 4, c16 = fi & 15;
        uint4 v = *(uint4*)(stage + row * 256 + ((c16 * 16) ^ ((row & 7) << 4)));
        *(uint4*)&g_D2h[(size_t)(i0 + row) * n + j0 + c16 * 8] = v;
    }
}

// ---------------- K: alpha — mu_num = W1 @ x, S1 sums ----------------
// dyn smem: Wh 0 (16K), xh 16384 (8K), xl 24576 (8K) -> 32768
__global__ void __launch_bounds__(256) k_alpha(const float* __restrict__ pr0, int n) {
    extern __shared__ char smc[];
    uint32_t sb = su32(smc);
    const int t = threadIdx.x, w = t >> 5, lane = t & 31;
    const int j0 = blockIdx.x * 128;
    const int ibase0 = blockIdx.y * 512;
    const float r0v = fminf(*pr0, sqrtf(__uint_as_float(g_maxbits)));
    const float R2i = 1.0f / (r0v * r0v);

    float C[8][4];
    #pragma unroll
    for (int b = 0; b < 8; b++)
        #pragma unroll
        for (int e = 0; e < 4; e++) C[b][e] = 0.f;

    for (int ch = 0; ch < 8; ch++) {
        int ib = ibase0 + ch * 64;
        if (ch) __syncthreads();
        for (int q = t; q < 512; q += 256) {
            int row = q >> 3, cb = (q & 7) * 16;
            uint32_t off = SWZ(row * 128 + cb);
            *(uint4*)(smc + 16384 + off) = *(const uint4*)&g_xh[(size_t)(ib + row) * P + cb / 2];
            *(uint4*)(smc + 24576 + off) = *(const uint4*)&g_xl[(size_t)(ib + row) * P + cb / 2];
        }
        {
            int j = t >> 1, ih = (t & 1) * 32;
            const __half* drow = &g_D2h[(size_t)(j0 + j) * n + ib + ih];
            float s = 0.f;
            #pragma unroll
            for (int q = 0; q < 4; q++) {
                uint4 dv4 = *(const uint4*)&drow[q * 8];
                uint32_t din[4] = {dv4.x, dv4.y, dv4.z, dv4.w};
                uint32_t hh[4];
                #pragma unroll
                for (int k = 0; k < 4; k++) {
                    float2 d2f = __half22float2(*(__half2*)&din[k]);
                    float w0 = w1f(d2f.x, R2i), w1v = w1f(d2f.y, R2i);
                    s += w0 + w1v;
                    hh[k] = packh2(w0, w1v);
                }
                *(uint4*)(smc + SWZ(j * 128 + (ih + q * 8) * 2)) = *(uint4*)hh;
            }
            s += __shfl_xor_sync(0xffffffffu, s, 1);
            if ((t & 1) == 0) atomicAdd(&g_S1[j0 + j], s);
        }
        __syncthreads();
        #pragma unroll
        for (int ks = 0; ks < 4; ks++) {
            int k0 = ks * 16;
            uint32_t Awh[4];
            ldm_x4(Awh, frag_addr(sb, lane, w * 16, k0));
            #pragma unroll
            for (int gq = 0; gq < 4; gq++) {
                uint32_t Bh[4], Bl[4];
                ldm_x4t(Bh, frag_addr(sb + 16384, lane, k0, gq * 16));
                ldm_x4t(Bl, frag_addr(sb + 24576, lane, k0, gq * 16));
                #pragma unroll
                for (int h = 0; h < 2; h++) {
                    int ni = gq * 2 + h;
                    uint32_t bh[2] = {Bh[h * 2], Bh[h * 2 + 1]};
                    uint32_t bl[2] = {Bl[h * 2], Bl[h * 2 + 1]};
                    mma16816(C[ni], Awh, bh);
                    mma16816(C[ni], Awh, bl);
                }
            }
        }
    }
    const int g = lane >> 2, tg = lane & 3;
    #pragma unroll
    for (int ni = 0; ni < 8; ni++)
        #pragma unroll
        for (int e = 0; e < 4; e++) {
            int j = j0 + w * 16 + g + (e >> 1) * 8;
            int p = ni * 8 + tg * 2 + (e & 1);
            atomicAdd(&g_mun[(size_t)j * P + p], C[ni][e]);
        }
}

// ---------------- K: U = x - mu (+ fp16 splits), bU, sqrt(||U||^2) ----------------
__global__ void k_U(const float* __restrict__ x, int n) {
    int w = (blockIdx.x * blockDim.x + threadIdx.x) >> 5;
    int lane = threadIdx.x & 31;
    if (w >= n) return;
    float S1 = g_S1[w];
    float b = 0.f, un2 = 0.f;
    #pragma unroll
    for (int h = 0; h < 2; h++) {
        int p = lane + 32 * h;
        float mu = g_mun[(size_t)w * P + p] / S1;
        float xv = x[(size_t)w * P + p];
        if (isnan(mu)) mu = xv;
        float U = xv - mu;
        __half uh = __float2half_rn(U);
        g_Uh[(size_t)w * P + p] = uh;
        g_Ul[(size_t)w * P + p] = __float2half_rn(U - __half2float(uh));
        b += xv * U;
        un2 += U * U;
    }
    #pragma unroll
    for (int o = 16; o; o >>= 1) {
        b += __shfl_xor_sync(0xffffffffu, b, o);
        un2 += __shfl_xor_sync(0xffffffffu, un2, o);
    }
    if (lane == 0) { g_bU[w] = b; g_sU2[w] = sqrtf(un2); }
}

// ---------------- K: beta — c-GEMM(x3) + weights + acc-GEMM(x2) ----------------
// dyn smem: Wh 0 (16K), Dst 16384 (16K), xh 32768 (8K), xl 40960 (8K),
//           bU 49152(512), su2 49664(512) -> 50176
__global__ void __launch_bounds__(256) k_beta(const float* __restrict__ pr1,
                                              const float* __restrict__ pr2, int n) {
    extern __shared__ char smc[];
    uint32_t sb = su32(smc);
    float* bUs  = (float*)(smc + 49152);
    float* su2s = (float*)(smc + 49664);
    const int t = threadIdx.x, w = t >> 5, lane = t & 31;
    const int j0 = blockIdx.x * 128;
    const int ibase0 = blockIdx.y * 512;
    const float md = sqrtf(__uint_as_float(g_maxbits));
    const float rr1 = fminf(*pr1, md), rr2 = fminf(*pr2, md);
    const float a1 = 2.0f / rr1, a2 = 2.0f / rr2;
    const int g = lane >> 2, tg = lane & 3;

    // stage U hi/lo, grab A fragments, then release the buffers
    for (int q = t; q < 1024; q += 256) {
        int row = q >> 3, cb = (q & 7) * 16;
        uint32_t off = SWZ(row * 128 + cb);
        *(uint4*)(smc + off)         = *(const uint4*)&g_Uh[(size_t)(j0 + row) * P + cb / 2];
        *(uint4*)(smc + 16384 + off) = *(const uint4*)&g_Ul[(size_t)(j0 + row) * P + cb / 2];
    }
    if (t < 128) { bUs[t] = g_bU[j0 + t]; su2s[t] = g_sU2[j0 + t]; }
    __syncthreads();
    uint32_t AUh[4][4], AUl[4][4];
    #pragma unroll
    for (int ks = 0; ks < 4; ks++) {
        ldm_x4(AUh[ks], frag_addr(sb,         lane, w * 16, ks * 16));
        ldm_x4(AUl[ks], frag_addr(sb + 16384, lane, w * 16, ks * 16));
    }
    __syncthreads();

    float accC[8][4];
    #pragma unroll
    for (int b = 0; b < 8; b++)
        #pragma unroll
        for (int e = 0; e < 4; e++) accC[b][e] = 0.f;

    for (int ch = 0; ch < 8; ch++) {
        int ib = ibase0 + ch * 64;
        if (ch) __syncthreads();
        for (int q = t; q < 512; q += 256) {
            int row = q >> 3, cb = (q & 7) * 16;
            uint32_t off = SWZ(row * 128 + cb);
            *(uint4*)(smc + 32768 + off) = *(const uint4*)&g_xh[(size_t)(ib + row) * P + cb / 2];
            *(uint4*)(smc + 40960 + off) = *(const uint4*)&g_xl[(size_t)(ib + row) * P + cb / 2];
        }
        // coalesced D2h tile load into swizzled stage [128 j][64 i]
        for (int q = t; q < 1024; q += 256) {
            int j = q >> 3, c = q & 7;
            *(uint4*)(smc + 16384 + j * 128 + ((c * 16) ^ ((j & 7) << 4))) =
                *(const uint4*)&g_D2h[(size_t)(j0 + j) * n + ib + c * 8];
        }
        __syncthreads();
        // c-GEMM: c[j][i] = U_j . x_i (3 terms)
        float cC[8][4];
        #pragma unroll
        for (int b = 0; b < 8; b++)
            #pragma unroll
            for (int e = 0; e < 4; e++) cC[b][e] = 0.f;
        #pragma unroll
        for (int ks = 0; ks < 4; ks++) {
            int k0 = ks * 16;
            #pragma unroll
            for (int gq = 0; gq < 4; gq++) {
                uint32_t Bh[4], Bl[4];
                ldm_x4(Bh, frag_addr(sb + 32768, lane, gq * 16, k0));
                ldm_x4(Bl, frag_addr(sb + 40960, lane, gq * 16, k0));
                #pragma unroll
                for (int h = 0; h < 2; h++) {
                    int ni = gq * 2 + h;
                    uint32_t bh[2] = {Bh[h], Bh[h + 2]};
                    uint32_t bl[2] = {Bl[h], Bl[h + 2]};
                    mma16816(cC[ni], AUh[ks], bh);
                    mma16816(cC[ni], AUh[ks], bl);
                    mma16816(cC[ni], AUl[ks], bh);
                }
            }
        }
        // weights -> Wh smem (fp16), row sums -> g_S2
        #pragma unroll
        for (int e2 = 0; e2 < 2; e2++) {
            int jl = w * 16 + g + e2 * 8;
            float bj = bUs[jl], su2 = su2s[jl];
            float rs = 0.f;
            #pragma unroll
            for (int ni = 0; ni < 8; ni++) {
                int il = ni * 8 + tg * 2;
                float2 dd = __half22float2(
                    *(__half2*)(smc + 16384 + jl * 128 + ((il * 2) ^ ((jl & 7) << 4))));
                float wv[2], d2v[2] = {dd.x, dd.y};
                #pragma unroll
                for (int q = 0; q < 2; q++) {
                    float cp = cC[ni][e2 * 2 + q] - bj;
                    float du = fmaxf(fabsf(cp) * su2, 1e-3f);
                    float dv = asqrt(fmaxf(d2v[q] - du * du, 1e-6f));
                    wv[q] = w2f(dv, a1) * w2f(du, a2);
                }
                rs += wv[0] + wv[1];
                *(uint32_t*)(smc + SWZ(jl * 128 + il * 2)) = packh2(wv[0], wv[1]);
            }
            rs += __shfl_xor_sync(0xffffffffu, rs, 1);
            rs += __shfl_xor_sync(0xffffffffu, rs, 2);
            if (tg == 0) atomicAdd(&g_S2[j0 + jl], rs);
        }
        __syncthreads();
        // acc-GEMM: acc[j][p] += W[j][i] x[i][p] (2 terms)
        #pragma unroll
        for (int ks = 0; ks < 4; ks++) {
            int k0 = ks * 16;
            uint32_t Awh[4];
            ldm_x4(Awh, frag_addr(sb, lane, w * 16, k0));
            #pragma unroll
            for (int gq = 0; gq < 4; gq++) {
                uint32_t Bh[4], Bl[4];
                ldm_x4t(Bh, frag_addr(sb + 32768, lane, k0, gq * 16));
                ldm_x4t(Bl, frag_addr(sb + 40960, lane, k0, gq * 16));
                #pragma unroll
                for (int h = 0; h < 2; h++) {
                    int ni = gq * 2 + h;
                    uint32_t bh[2] = {Bh[h * 2], Bh[h * 2 + 1]};
                    uint32_t bl[2] = {Bl[h * 2], Bl[h * 2 + 1]};
                    mma16816(accC[ni], Awh, bh);
                    mma16816(accC[ni], Awh, bl);
                }
            }
        }
    }
    #pragma unroll
    for (int ni = 0; ni < 8; ni++)
        #pragma unroll
        for (int e = 0; e < 4; e++) {
            int j = j0 + w * 16 + g + (e >> 1) * 8;
            int p = ni * 8 + tg * 2 + (e & 1);
            atomicAdd(&g_accZ[(size_t)j * P + p], accC[ni][e]);
        }
}

// ---------------- K: output ----------------
__global__ void k_out(const float* __restrict__ x, float* __restrict__ out, int n) {
    int idx = blockIdx.x * blockDim.x + threadIdx.x;
    if (idx >= n * P) return;
    int j = idx >> 6;
    float e = g_accZ[idx] / g_S2[j];
    if (isnan(e)) e = x[idx];
    out[idx] = e;
}

extern "C" void kernel_launch(void* const* d_in, const int* in_sizes, int n_in,
                              void* d_out, int out_size) {
    const float* x  = (const float*)d_in[0];
    const float* r0 = (const float*)d_in[1];
    const float* r1 = (const float*)d_in[2];
    const float* r2 = (const float*)d_in[3];
    float* out = (float*)d_out;
    const int n = in_sizes[0] / P;  // 4096

    void *pMax, *pS1, *pMun, *pS2, *pAcc;
    cudaGetSymbolAddress(&pMax, g_maxbits);
    cudaGetSymbolAddress(&pS1, g_S1);
    cudaGetSymbolAddress(&pMun, g_mun);
    cudaGetSymbolAddress(&pS2, g_S2);
    cudaGetSymbolAddress(&pAcc, g_accZ);
    cudaMemsetAsync(pMax, 0, sizeof(unsigned int));
    cudaMemsetAsync(pS1, 0, (size_t)n * sizeof(float));
    cudaMemsetAsync(pMun, 0, (size_t)n * P * sizeof(float));
    cudaMemsetAsync(pS2, 0, (size_t)n * sizeof(float));
    cudaMemsetAsync(pAcc, 0, (size_t)n * P * sizeof(float));

    k_sq<<<(n + 7) / 8, 256>>>(x, n);
    k_prep<<<(n * P / 4 + 255) / 256, 256>>>(x, n * P / 4);

    cudaFuncSetAttribute(k_gram, cudaFuncAttributeMaxDynamicSharedMemorySize, 66560);
    k_gram<<<dim3(n / 128, n / 128), 256, 66560>>>(n);

    cudaFuncSetAttribute(k_alpha, cudaFuncAttributeMaxDynamicSharedMemorySize, 32768);
    k_alpha<<<dim3(n / 128, 8), 256, 32768>>>(r0, n);

    k_U<<<(n + 7) / 8, 256>>>(x, n);

    cudaFuncSetAttribute(k_beta, cudaFuncAttributeMaxDynamicSharedMemorySize, 50176);
    k_beta<<<dim3(n / 128, 8), 256, 50176>>>(r1, r2, n);

    k_out<<<(n * P + 255) / 256, 256>>>(x, out, n);
}

// round 6
// speedup vs baseline: 2.1711x; 1.1107x over previous
#include <cuda_runtime.h>
#include <cuda_fp16.h>
#include <math.h>
#include <stdint.h>

#define P 64
#define NMAX 4096

// ---------------- persistent device scratch ----------------
__device__ float g_sq[NMAX];
__device__ __half g_D2h[(size_t)NMAX * NMAX];   // 32 MB pairwise squared distances (fp16)
__device__ unsigned int g_maxbits;
__device__ float g_S1[NMAX];
__device__ float g_mun[NMAX * P];
__device__ float g_bU[NMAX];
__device__ float g_sU2[NMAX];                   // sqrt(||U_j||^2)
__device__ float g_S2[NMAX];
__device__ float g_accZ[NMAX * P];
__device__ __half g_xh[NMAX * P], g_xl[NMAX * P];
__device__ __half g_Uh[NMAX * P], g_Ul[NMAX * P];

// ---------------- helpers ----------------
__device__ __forceinline__ uint32_t su32(const void* p) {
    uint32_t a;
    asm("{ .reg .u64 t; cvta.to.shared.u64 t, %1; cvt.u32.u64 %0, t; }" : "=r"(a) : "l"(p));
    return a;
}
#define SWZ(b) ((uint32_t)(b) ^ ((((uint32_t)(b)) >> 3) & 0x70))

__device__ __forceinline__ uint32_t frag_addr(uint32_t base, int lane, int row0, int col0) {
    int r = row0 + (lane & 7) + ((lane >> 3) & 1) * 8;
    int cb = (col0 + (lane >> 4) * 8) * 2;
    return base + SWZ(r * 128 + cb);
}
__device__ __forceinline__ void ldm_x4(uint32_t* r, uint32_t a) {
    asm volatile("ldmatrix.sync.aligned.m8n8.x4.shared.b16 {%0,%1,%2,%3}, [%4];"
                 : "=r"(r[0]), "=r"(r[1]), "=r"(r[2]), "=r"(r[3]) : "r"(a));
}
__device__ __forceinline__ void ldm_x4t(uint32_t* r, uint32_t a) {
    asm volatile("ldmatrix.sync.aligned.m8n8.x4.trans.shared.b16 {%0,%1,%2,%3}, [%4];"
                 : "=r"(r[0]), "=r"(r[1]), "=r"(r[2]), "=r"(r[3]) : "r"(a));
}
__device__ __forceinline__ void mma16816(float* c, const uint32_t* a, const uint32_t* b) {
    asm volatile(
        "mma.sync.aligned.m16n8k16.row.col.f32.f16.f16.f32 "
        "{%0,%1,%2,%3}, {%4,%5,%6,%7}, {%8,%9}, {%0,%1,%2,%3};"
        : "+f"(c[0]), "+f"(c[1]), "+f"(c[2]), "+f"(c[3])
        : "r"(a[0]), "r"(a[1]), "r"(a[2]), "r"(a[3]), "r"(b[0]), "r"(b[1]));
}
__device__ __forceinline__ uint32_t packh2(float a, float b) {
    __half2 h = __floats2half2_rn(a, b);
    return *(uint32_t*)&h;
}
__device__ __forceinline__ float asqrt(float x) { float r; asm("sqrt.approx.f32 %0,%1;" : "=f"(r) : "f"(x)); return r; }
__device__ __forceinline__ float w1f(float d2, float R2i) {
    float s = fmaxf(fmaf(-d2, R2i, 1.0f), 0.0f);
    return s * s * s;
}
__device__ __forceinline__ float w2f(float d, float a /* = 2/r */) {
    float t = __saturatef(fmaf(d, a, -1.0f));
    float s = fmaf(-t, t, 1.0f);
    return s * s * s;
}

// ---------------- K: prep — sq norms + fp16 hi/lo split ----------------
__global__ void k_prep(const float* __restrict__ x, int n) {
    int w = (blockIdx.x * blockDim.x + threadIdx.x) >> 5;
    int lane = threadIdx.x & 31;
    if (w >= n) return;
    float v0 = x[(size_t)w * P + lane], v1 = x[(size_t)w * P + 32 + lane];
    __half h0 = __float2half_rn(v0), h1 = __float2half_rn(v1);
    g_xh[(size_t)w * P + lane] = h0;
    g_xh[(size_t)w * P + 32 + lane] = h1;
    g_xl[(size_t)w * P + lane] = __float2half_rn(v0 - __half2float(h0));
    g_xl[(size_t)w * P + 32 + lane] = __float2half_rn(v1 - __half2float(h1));
    float s = v0 * v0 + v1 * v1;
    #pragma unroll
    for (int o = 16; o; o >>= 1) s += __shfl_xor_sync(0xffffffffu, s, o);
    if (lane == 0) g_sq[w] = s;
}

// ---------------- K: gram -> D2h via HMMA (fp16 x2), smem-staged fp16 store ----------------
// dyn smem: Ah 0 (16K), Bh 16384 (16K), Bl 32768 (16K); stage reuses 16384..49152;
//           sqi 49152(512), sqj 49664(512) -> 50176
__global__ void __launch_bounds__(256) k_gram(int n) {
    extern __shared__ char smc[];
    __shared__ float wmax[8];
    uint32_t sb = su32(smc);
    const int t = threadIdx.x, w = t >> 5, lane = t & 31;
    const int i0 = blockIdx.y * 128, j0 = blockIdx.x * 128;
    float* sqi = (float*)(smc + 49152);
    float* sqj = (float*)(smc + 49664);
    char* stage = smc + 16384;

    for (int q = t; q < 1024; q += 256) {
        int row = q >> 3, cb = (q & 7) * 16;
        uint32_t off = SWZ(row * 128 + cb);
        *(uint4*)(smc + off)         = *(const uint4*)&g_xh[(size_t)(i0 + row) * P + cb / 2];
        *(uint4*)(smc + 16384 + off) = *(const uint4*)&g_xh[(size_t)(j0 + row) * P + cb / 2];
        *(uint4*)(smc + 32768 + off) = *(const uint4*)&g_xl[(size_t)(j0 + row) * P + cb / 2];
    }
    if (t < 128) sqi[t] = g_sq[i0 + t];
    else sqj[t - 128] = g_sq[j0 + t - 128];
    __syncthreads();

    const int m0 = (w & 3) * 32, n0w = (w >> 2) * 64;
    float C[2][8][4];
    #pragma unroll
    for (int a = 0; a < 2; a++)
        #pragma unroll
        for (int b = 0; b < 8; b++)
            #pragma unroll
            for (int e = 0; e < 4; e++) C[a][b][e] = 0.f;

    #pragma unroll
    for (int ks = 0; ks < 4; ks++) {
        int k0 = ks * 16;
        uint32_t Ah[2][4];
        #pragma unroll
        for (int mi = 0; mi < 2; mi++)
            ldm_x4(Ah[mi], frag_addr(sb, lane, m0 + mi * 16, k0));
        #pragma unroll
        for (int gq = 0; gq < 4; gq++) {
            uint32_t Bh[4], Bl[4];
            ldm_x4(Bh, frag_addr(sb + 16384, lane, n0w + gq * 16, k0));
            ldm_x4(Bl, frag_addr(sb + 32768, lane, n0w + gq * 16, k0));
            #pragma unroll
            for (int h = 0; h < 2; h++) {
                int ni = gq * 2 + h;
                uint32_t bh[2] = {Bh[h], Bh[h + 2]};
                uint32_t bl[2] = {Bl[h], Bl[h + 2]};
                #pragma unroll
                for (int mi = 0; mi < 2; mi++) {
                    mma16816(C[mi][ni], Ah[mi], bh);
                    mma16816(C[mi][ni], Ah[mi], bl);
                }
            }
        }
    }
    __syncthreads();  // B-tile reads done -> reuse as fp16 stage

    const int g = lane >> 2, tg = lane & 3;
    float lmax = 0.f;
    #pragma unroll
    for (int mi = 0; mi < 2; mi++)
        #pragma unroll
        for (int e2 = 0; e2 < 2; e2++) {
            int i = m0 + mi * 16 + g + e2 * 8;
            float si = sqi[i];
            #pragma unroll
            for (int ni = 0; ni < 8; ni++) {
                int j = n0w + ni * 8 + tg * 2;
                float d0 = fmaxf(si + sqj[j]     - 2.f * C[mi][ni][e2 * 2],     0.f);
                float d1 = fmaxf(si + sqj[j + 1] - 2.f * C[mi][ni][e2 * 2 + 1], 0.f);
                lmax = fmaxf(lmax, fmaxf(d0, d1));
                *(uint32_t*)(stage + i * 256 + ((j * 2) ^ ((i & 7) << 4))) = packh2(d0, d1);
            }
        }
    #pragma unroll
    for (int o = 16; o; o >>= 1) lmax = fmaxf(lmax, __shfl_xor_sync(0xffffffffu, lmax, o));
    if (lane == 0) wmax[w] = lmax;
    __syncthreads();
    if (t == 0) {
        float m = wmax[0];
        #pragma unroll
        for (int q = 1; q < 8; q++) m = fmaxf(m, wmax[q]);
        atomicMax(&g_maxbits, __float_as_uint(m));
    }
    #pragma unroll
    for (int m = 0; m < 8; m++) {
        int fi = t + 256 * m;
        int row = fi >> 4, c16 = fi & 15;
        uint4 v = *(uint4*)(stage + row * 256 + ((c16 * 16) ^ ((row & 7) << 4)));
        *(uint4*)&g_D2h[(size_t)(i0 + row) * n + j0 + c16 * 8] = v;
    }
}

// ---------------- K: alpha — mu_num = W1 @ x (1 term), S1 sums ----------------
// dyn smem: Wh 0 (16K), xh 16384 (8K) -> 24576 ; grid (n/128, 32), 2 chunks/block
__global__ void __launch_bounds__(256) k_alpha(const float* __restrict__ pr0, int n) {
    extern __shared__ char smc[];
    uint32_t sb = su32(smc);
    const int t = threadIdx.x, w = t >> 5, lane = t & 31;
    const int j0 = blockIdx.x * 128;
    const int ibase0 = blockIdx.y * 128;
    const float r0v = fminf(*pr0, sqrtf(__uint_as_float(g_maxbits)));
    const float R2i = 1.0f / (r0v * r0v);

    float C[8][4];
    #pragma unroll
    for (int b = 0; b < 8; b++)
        #pragma unroll
        for (int e = 0; e < 4; e++) C[b][e] = 0.f;

    #pragma unroll
    for (int ch = 0; ch < 2; ch++) {
        int ib = ibase0 + ch * 64;
        if (ch) __syncthreads();
        for (int q = t; q < 512; q += 256) {
            int row = q >> 3, cb = (q & 7) * 16;
            *(uint4*)(smc + 16384 + SWZ(row * 128 + cb)) =
                *(const uint4*)&g_xh[(size_t)(ib + row) * P + cb / 2];
        }
        {
            int j = t >> 1, ih = (t & 1) * 32;
            const __half* drow = &g_D2h[(size_t)(j0 + j) * n + ib + ih];
            float s = 0.f;
            #pragma unroll
            for (int q = 0; q < 4; q++) {
                uint4 dv4 = *(const uint4*)&drow[q * 8];
                uint32_t din[4] = {dv4.x, dv4.y, dv4.z, dv4.w};
                uint32_t hh[4];
                #pragma unroll
                for (int k = 0; k < 4; k++) {
                    float2 d2f = __half22float2(*(__half2*)&din[k]);
                    float w0 = w1f(d2f.x, R2i), w1v = w1f(d2f.y, R2i);
                    s += w0 + w1v;
                    hh[k] = packh2(w0, w1v);
                }
                *(uint4*)(smc + SWZ(j * 128 + (ih + q * 8) * 2)) = *(uint4*)hh;
            }
            s += __shfl_xor_sync(0xffffffffu, s, 1);
            if ((t & 1) == 0) atomicAdd(&g_S1[j0 + j], s);
        }
        __syncthreads();
        #pragma unroll
        for (int ks = 0; ks < 4; ks++) {
            int k0 = ks * 16;
            uint32_t Awh[4];
            ldm_x4(Awh, frag_addr(sb, lane, w * 16, k0));
            #pragma unroll
            for (int gq = 0; gq < 4; gq++) {
                uint32_t Bh[4];
                ldm_x4t(Bh, frag_addr(sb + 16384, lane, k0, gq * 16));
                #pragma unroll
                for (int h = 0; h < 2; h++) {
                    uint32_t bh[2] = {Bh[h * 2], Bh[h * 2 + 1]};
                    mma16816(C[gq * 2 + h], Awh, bh);
                }
            }
        }
    }
    const int g = lane >> 2, tg = lane & 3;
    #pragma unroll
    for (int ni = 0; ni < 8; ni++)
        #pragma unroll
        for (int e = 0; e < 4; e++) {
            int j = j0 + w * 16 + g + (e >> 1) * 8;
            int p = ni * 8 + tg * 2 + (e & 1);
            atomicAdd(&g_mun[(size_t)j * P + p], C[ni][e]);
        }
}

// ---------------- K: U = x - mu (+ fp16 splits), bU, sqrt(||U||^2) ----------------
__global__ void k_U(const float* __restrict__ x, int n) {
    int w = (blockIdx.x * blockDim.x + threadIdx.x) >> 5;
    int lane = threadIdx.x & 31;
    if (w >= n) return;
    float S1 = g_S1[w];
    float b = 0.f, un2 = 0.f;
    #pragma unroll
    for (int h = 0; h < 2; h++) {
        int p = lane + 32 * h;
        float mu = g_mun[(size_t)w * P + p] / S1;
        float xv = x[(size_t)w * P + p];
        if (isnan(mu)) mu = xv;
        float U = xv - mu;
        __half uh = __float2half_rn(U);
        g_Uh[(size_t)w * P + p] = uh;
        g_Ul[(size_t)w * P + p] = __float2half_rn(U - __half2float(uh));
        b += xv * U;
        un2 += U * U;
    }
    #pragma unroll
    for (int o = 16; o; o >>= 1) {
        b += __shfl_xor_sync(0xffffffffu, b, o);
        un2 += __shfl_xor_sync(0xffffffffu, un2, o);
    }
    if (lane == 0) { g_bU[w] = b; g_sU2[w] = sqrtf(un2); }
}

// ---------------- K: beta — c-GEMM(x3) + weights + acc-GEMM(x1) ----------------
// dyn smem: Wh 0 (16K), Dst 16384 (16K), xh 32768 (8K), xl 40960 (8K),
//           bU 49152(512), su2 49664(512) -> 50176 ; grid (n/128, 16), 4 chunks
__global__ void __launch_bounds__(256) k_beta(const float* __restrict__ pr1,
                                              const float* __restrict__ pr2, int n) {
    extern __shared__ char smc[];
    uint32_t sb = su32(smc);
    float* bUs  = (float*)(smc + 49152);
    float* su2s = (float*)(smc + 49664);
    const int t = threadIdx.x, w = t >> 5, lane = t & 31;
    const int j0 = blockIdx.x * 128;
    const int ibase0 = blockIdx.y * 256;
    const float md = sqrtf(__uint_as_float(g_maxbits));
    const float rr1 = fminf(*pr1, md), rr2 = fminf(*pr2, md);
    const float a1 = 2.0f / rr1, a2 = 2.0f / rr2;
    const int g = lane >> 2, tg = lane & 3;

    for (int q = t; q < 1024; q += 256) {
        int row = q >> 3, cb = (q & 7) * 16;
        uint32_t off = SWZ(row * 128 + cb);
        *(uint4*)(smc + off)         = *(const uint4*)&g_Uh[(size_t)(j0 + row) * P + cb / 2];
        *(uint4*)(smc + 16384 + off) = *(const uint4*)&g_Ul[(size_t)(j0 + row) * P + cb / 2];
    }
    if (t < 128) { bUs[t] = g_bU[j0 + t]; su2s[t] = g_sU2[j0 + t]; }
    __syncthreads();
    uint32_t AUh[4][4], AUl[4][4];
    #pragma unroll
    for (int ks = 0; ks < 4; ks++) {
        ldm_x4(AUh[ks], frag_addr(sb,         lane, w * 16, ks * 16));
        ldm_x4(AUl[ks], frag_addr(sb + 16384, lane, w * 16, ks * 16));
    }
    __syncthreads();

    float accC[8][4];
    #pragma unroll
    for (int b = 0; b < 8; b++)
        #pragma unroll
        for (int e = 0; e < 4; e++) accC[b][e] = 0.f;

    #pragma unroll 1
    for (int ch = 0; ch < 4; ch++) {
        int ib = ibase0 + ch * 64;
        if (ch) __syncthreads();
        for (int q = t; q < 512; q += 256) {
            int row = q >> 3, cb = (q & 7) * 16;
            uint32_t off = SWZ(row * 128 + cb);
            *(uint4*)(smc + 32768 + off) = *(const uint4*)&g_xh[(size_t)(ib + row) * P + cb / 2];
            *(uint4*)(smc + 40960 + off) = *(const uint4*)&g_xl[(size_t)(ib + row) * P + cb / 2];
        }
        for (int q = t; q < 1024; q += 256) {
            int j = q >> 3, c = q & 7;
            *(uint4*)(smc + 16384 + j * 128 + ((c * 16) ^ ((j & 7) << 4))) =
                *(const uint4*)&g_D2h[(size_t)(j0 + j) * n + ib + c * 8];
        }
        __syncthreads();
        float cC[8][4];
        #pragma unroll
        for (int b = 0; b < 8; b++)
            #pragma unroll
            for (int e = 0; e < 4; e++) cC[b][e] = 0.f;
        #pragma unroll
        for (int ks = 0; ks < 4; ks++) {
            int k0 = ks * 16;
            #pragma unroll
            for (int gq = 0; gq < 4; gq++) {
                uint32_t Bh[4], Bl[4];
                ldm_x4(Bh, frag_addr(sb + 32768, lane, gq * 16, k0));
                ldm_x4(Bl, frag_addr(sb + 40960, lane, gq * 16, k0));
                #pragma unroll
                for (int h = 0; h < 2; h++) {
                    int ni = gq * 2 + h;
                    uint32_t bh[2] = {Bh[h], Bh[h + 2]};
                    uint32_t bl[2] = {Bl[h], Bl[h + 2]};
                    mma16816(cC[ni], AUh[ks], bh);
                    mma16816(cC[ni], AUh[ks], bl);
                    mma16816(cC[ni], AUl[ks], bh);
                }
            }
        }
        #pragma unroll
        for (int e2 = 0; e2 < 2; e2++) {
            int jl = w * 16 + g + e2 * 8;
            float bj = bUs[jl], su2 = su2s[jl];
            float rs = 0.f;
            #pragma unroll
            for (int ni = 0; ni < 8; ni++) {
                int il = ni * 8 + tg * 2;
                float2 dd = __half22float2(
                    *(__half2*)(smc + 16384 + jl * 128 + ((il * 2) ^ ((jl & 7) << 4))));
                float wv[2], d2v[2] = {dd.x, dd.y};
                #pragma unroll
                for (int q = 0; q < 2; q++) {
                    float cp = cC[ni][e2 * 2 + q] - bj;
                    float du = fmaxf(fabsf(cp) * su2, 1e-3f);
                    float dv = asqrt(fmaxf(d2v[q] - du * du, 1e-6f));
                    wv[q] = w2f(dv, a1) * w2f(du, a2);
                }
                rs += wv[0] + wv[1];
                *(uint32_t*)(smc + SWZ(jl * 128 + il * 2)) = packh2(wv[0], wv[1]);
            }
            rs += __shfl_xor_sync(0xffffffffu, rs, 1);
            rs += __shfl_xor_sync(0xffffffffu, rs, 2);
            if (tg == 0) atomicAdd(&g_S2[j0 + jl], rs);
        }
        __syncthreads();
        #pragma unroll
        for (int ks = 0; ks < 4; ks++) {
            int k0 = ks * 16;
            uint32_t Awh[4];
            ldm_x4(Awh, frag_addr(sb, lane, w * 16, k0));
            #pragma unroll
            for (int gq = 0; gq < 4; gq++) {
                uint32_t Bh[4];
                ldm_x4t(Bh, frag_addr(sb + 32768, lane, k0, gq * 16));
                #pragma unroll
                for (int h = 0; h < 2; h++) {
                    uint32_t bh[2] = {Bh[h * 2], Bh[h * 2 + 1]};
                    mma16816(accC[gq * 2 + h], Awh, bh);
                }
            }
        }
    }
    #pragma unroll
    for (int ni = 0; ni < 8; ni++)
        #pragma unroll
        for (int e = 0; e < 4; e++) {
            int j = j0 + w * 16 + g + (e >> 1) * 8;
            int p = ni * 8 + tg * 2 + (e & 1);
            atomicAdd(&g_accZ[(size_t)j * P + p], accC[ni][e]);
        }
}

// ---------------- K: output ----------------
__global__ void k_out(const float* __restrict__ x, float* __restrict__ out, int n) {
    int idx = blockIdx.x * blockDim.x + threadIdx.x;
    if (idx >= n * P) return;
    int j = idx >> 6;
    float e = g_accZ[idx] / g_S2[j];
    if (isnan(e)) e = x[idx];
    out[idx] = e;
}

extern "C" void kernel_launch(void* const* d_in, const int* in_sizes, int n_in,
                              void* d_out, int out_size) {
    const float* x  = (const float*)d_in[0];
    const float* r0 = (const float*)d_in[1];
    const float* r1 = (const float*)d_in[2];
    const float* r2 = (const float*)d_in[3];
    float* out = (float*)d_out;
    const int n = in_sizes[0] / P;  // 4096

    void *pMax, *pS1, *pMun, *pS2, *pAcc;
    cudaGetSymbolAddress(&pMax, g_maxbits);
    cudaGetSymbolAddress(&pS1, g_S1);
    cudaGetSymbolAddress(&pMun, g_mun);
    cudaGetSymbolAddress(&pS2, g_S2);
    cudaGetSymbolAddress(&pAcc, g_accZ);
    cudaMemsetAsync(pMax, 0, sizeof(unsigned int));
    cudaMemsetAsync(pS1, 0, (size_t)n * sizeof(float));
    cudaMemsetAsync(pMun, 0, (size_t)n * P * sizeof(float));
    cudaMemsetAsync(pS2, 0, (size_t)n * sizeof(float));
    cudaMemsetAsync(pAcc, 0, (size_t)n * P * sizeof(float));

    k_prep<<<(n + 7) / 8, 256>>>(x, n);

    cudaFuncSetAttribute(k_gram, cudaFuncAttributeMaxDynamicSharedMemorySize, 50176);
    k_gram<<<dim3(n / 128, n / 128), 256, 50176>>>(n);

    cudaFuncSetAttribute(k_alpha, cudaFuncAttributeMaxDynamicSharedMemorySize, 24576);
    k_alpha<<<dim3(n / 128, 32), 256, 24576>>>(r0, n);

    k_U<<<(n + 7) / 8, 256>>>(x, n);

    cudaFuncSetAttribute(k_beta, cudaFuncAttributeMaxDynamicSharedMemorySize, 50176);
    k_beta<<<dim3(n / 128, 16), 256, 50176>>>(r1, r2, n);

    k_out<<<(n * P + 255) / 256, 256>>>(x, out, n);
}

// round 7
// speedup vs baseline: 2.3274x; 1.0720x over previous
#include <cuda_runtime.h>
#include <cuda_fp16.h>
#include <math.h>
#include <stdint.h>

#define P 64
#define NMAX 4096

// ---------------- persistent device scratch ----------------
__device__ float g_sq[NMAX];
__device__ __half g_D2h[(size_t)NMAX * NMAX];   // 32 MB pairwise squared distances (fp16)
__device__ unsigned int g_maxbits;
__device__ float g_S1[NMAX];
__device__ float g_mun[NMAX * P];
__device__ float g_bU[NMAX];
__device__ float g_sU2[NMAX];
__device__ float g_S2[NMAX];
__device__ float g_accZ[NMAX * P];
__device__ __half g_xh[NMAX * P], g_xl[NMAX * P];
__device__ __half g_Uh[NMAX * P], g_Ul[NMAX * P];

// ---------------- helpers ----------------
__device__ __forceinline__ uint32_t su32(const void* p) {
    uint32_t a;
    asm("{ .reg .u64 t; cvta.to.shared.u64 t, %1; cvt.u32.u64 %0, t; }" : "=r"(a) : "l"(p));
    return a;
}
#define SWZ(b) ((uint32_t)(b) ^ ((((uint32_t)(b)) >> 3) & 0x70))

__device__ __forceinline__ uint32_t frag_addr(uint32_t base, int lane, int row0, int col0) {
    int r = row0 + (lane & 7) + ((lane >> 3) & 1) * 8;
    int cb = (col0 + (lane >> 4) * 8) * 2;
    return base + SWZ(r * 128 + cb);
}
__device__ __forceinline__ void ldm_x4(uint32_t* r, uint32_t a) {
    asm volatile("ldmatrix.sync.aligned.m8n8.x4.shared.b16 {%0,%1,%2,%3}, [%4];"
                 : "=r"(r[0]), "=r"(r[1]), "=r"(r[2]), "=r"(r[3]) : "r"(a));
}
__device__ __forceinline__ void ldm_x4t(uint32_t* r, uint32_t a) {
    asm volatile("ldmatrix.sync.aligned.m8n8.x4.trans.shared.b16 {%0,%1,%2,%3}, [%4];"
                 : "=r"(r[0]), "=r"(r[1]), "=r"(r[2]), "=r"(r[3]) : "r"(a));
}
__device__ __forceinline__ void mma16816(float* c, const uint32_t* a, const uint32_t* b) {
    asm volatile(
        "mma.sync.aligned.m16n8k16.row.col.f32.f16.f16.f32 "
        "{%0,%1,%2,%3}, {%4,%5,%6,%7}, {%8,%9}, {%0,%1,%2,%3};"
        : "+f"(c[0]), "+f"(c[1]), "+f"(c[2]), "+f"(c[3])
        : "r"(a[0]), "r"(a[1]), "r"(a[2]), "r"(a[3]), "r"(b[0]), "r"(b[1]));
}
__device__ __forceinline__ uint32_t packh2(float a, float b) {
    __half2 h = __floats2half2_rn(a, b);
    return *(uint32_t*)&h;
}
__device__ __forceinline__ float asqrt(float x) { float r; asm("sqrt.approx.f32 %0,%1;" : "=f"(r) : "f"(x)); return r; }
__device__ __forceinline__ float w1f(float d2, float R2i) {
    float s = fmaxf(fmaf(-d2, R2i, 1.0f), 0.0f);
    return s * s * s;
}
__device__ __forceinline__ float w2f(float d, float a) {
    float t = __saturatef(fmaf(d, a, -1.0f));
    float s = fmaf(-t, t, 1.0f);
    return s * s * s;
}

// ---------------- K: prep — sq norms + fp16 split + zero-init (S1, mun, maxbits) ----------------
__global__ void k_prep(const float* __restrict__ x, int n) {
    int gt = blockIdx.x * blockDim.x + threadIdx.x;
    int w = gt >> 5;
    int lane = threadIdx.x & 31;
    // zero-init accumulators for this launch (replay-safe; runs before gram/alpha)
    *(float2*)&g_mun[(size_t)gt * 2] = make_float2(0.f, 0.f);
    if (gt < n) g_S1[gt] = 0.f;
    if (gt == 0) g_maxbits = 0u;
    if (w >= n) return;
    float v0 = x[(size_t)w * P + lane], v1 = x[(size_t)w * P + 32 + lane];
    __half h0 = __float2half_rn(v0), h1 = __float2half_rn(v1);
    g_xh[(size_t)w * P + lane] = h0;
    g_xh[(size_t)w * P + 32 + lane] = h1;
    g_xl[(size_t)w * P + lane] = __float2half_rn(v0 - __half2float(h0));
    g_xl[(size_t)w * P + 32 + lane] = __float2half_rn(v1 - __half2float(h1));
    float s = v0 * v0 + v1 * v1;
    #pragma unroll
    for (int o = 16; o; o >>= 1) s += __shfl_xor_sync(0xffffffffu, s, o);
    if (lane == 0) g_sq[w] = s;
}

// ---------------- K: gram (upper-triangle only) -> D2h, mirror store for off-diag ----------------
// dyn smem: Ah 0 (16K), Bh 16384 (16K), Bl 32768 (16K); stage reuses 16384..49152;
//           sqi 49152(512), sqj 49664(512) -> 50176
__global__ void __launch_bounds__(256) k_gram(int n) {
    extern __shared__ char smc[];
    __shared__ float wmax[8];
    uint32_t sb = su32(smc);
    const int t = threadIdx.x, w = t >> 5, lane = t & 31;
    // map linear block id -> upper-triangle tile (ti <= tj)
    const int nb = n >> 7;
    int k = blockIdx.x, a = 0;
    while (k >= nb - a) { k -= nb - a; a++; }
    const int ti = a, tj = a + k;
    const int i0 = ti * 128, j0 = tj * 128;
    float* sqi = (float*)(smc + 49152);
    float* sqj = (float*)(smc + 49664);
    char* stage = smc + 16384;

    for (int q = t; q < 1024; q += 256) {
        int row = q >> 3, cb = (q & 7) * 16;
        uint32_t off = SWZ(row * 128 + cb);
        *(uint4*)(smc + off)         = *(const uint4*)&g_xh[(size_t)(i0 + row) * P + cb / 2];
        *(uint4*)(smc + 16384 + off) = *(const uint4*)&g_xh[(size_t)(j0 + row) * P + cb / 2];
        *(uint4*)(smc + 32768 + off) = *(const uint4*)&g_xl[(size_t)(j0 + row) * P + cb / 2];
    }
    if (t < 128) sqi[t] = g_sq[i0 + t];
    else sqj[t - 128] = g_sq[j0 + t - 128];
    __syncthreads();

    const int m0 = (w & 3) * 32, n0w = (w >> 2) * 64;
    float C[2][8][4];
    #pragma unroll
    for (int a2 = 0; a2 < 2; a2++)
        #pragma unroll
        for (int b = 0; b < 8; b++)
            #pragma unroll
            for (int e = 0; e < 4; e++) C[a2][b][e] = 0.f;

    #pragma unroll
    for (int ks = 0; ks < 4; ks++) {
        int k0 = ks * 16;
        uint32_t Ah[2][4];
        #pragma unroll
        for (int mi = 0; mi < 2; mi++)
            ldm_x4(Ah[mi], frag_addr(sb, lane, m0 + mi * 16, k0));
        #pragma unroll
        for (int gq = 0; gq < 4; gq++) {
            uint32_t Bh[4], Bl[4];
            ldm_x4(Bh, frag_addr(sb + 16384, lane, n0w + gq * 16, k0));
            ldm_x4(Bl, frag_addr(sb + 32768, lane, n0w + gq * 16, k0));
            #pragma unroll
            for (int h = 0; h < 2; h++) {
                int ni = gq * 2 + h;
                uint32_t bh[2] = {Bh[h], Bh[h + 2]};
                uint32_t bl[2] = {Bl[h], Bl[h + 2]};
                #pragma unroll
                for (int mi = 0; mi < 2; mi++) {
                    mma16816(C[mi][ni], Ah[mi], bh);
                    mma16816(C[mi][ni], Ah[mi], bl);
                }
            }
        }
    }
    __syncthreads();  // B-tile reads done -> reuse as fp16 stage

    const int g = lane >> 2, tg = lane & 3;
    float lmax = 0.f;
    #pragma unroll
    for (int mi = 0; mi < 2; mi++)
        #pragma unroll
        for (int e2 = 0; e2 < 2; e2++) {
            int i = m0 + mi * 16 + g + e2 * 8;
            float si = sqi[i];
            #pragma unroll
            for (int ni = 0; ni < 8; ni++) {
                int j = n0w + ni * 8 + tg * 2;
                float d0 = fmaxf(si + sqj[j]     - 2.f * C[mi][ni][e2 * 2],     0.f);
                float d1 = fmaxf(si + sqj[j + 1] - 2.f * C[mi][ni][e2 * 2 + 1], 0.f);
                lmax = fmaxf(lmax, fmaxf(d0, d1));
                *(uint32_t*)(stage + i * 256 + ((j * 2) ^ ((i & 7) << 4))) = packh2(d0, d1);
            }
        }
    #pragma unroll
    for (int o = 16; o; o >>= 1) lmax = fmaxf(lmax, __shfl_xor_sync(0xffffffffu, lmax, o));
    if (lane == 0) wmax[w] = lmax;
    __syncthreads();
    if (t == 0) {
        float m = wmax[0];
        #pragma unroll
        for (int q = 1; q < 8; q++) m = fmaxf(m, wmax[q]);
        atomicMax(&g_maxbits, __float_as_uint(m));
    }
    // coalesced store of (i0, j0) tile
    #pragma unroll
    for (int m = 0; m < 8; m++) {
        int fi = t + 256 * m;
        int row = fi >> 4, c16 = fi & 15;
        uint4 v = *(uint4*)(stage + row * 256 + ((c16 * 16) ^ ((row & 7) << 4)));
        *(uint4*)&g_D2h[(size_t)(i0 + row) * n + j0 + c16 * 8] = v;
    }

    if (ti == tj) return;

    // mirror: rebuild stage transposed from live fragments, store (j0, i0) tile
    __syncthreads();
    #pragma unroll
    for (int mi = 0; mi < 2; mi++)
        #pragma unroll
        for (int e2 = 0; e2 < 2; e2++) {
            int i = m0 + mi * 16 + g + e2 * 8;
            float si = sqi[i];
            #pragma unroll
            for (int ni = 0; ni < 8; ni++) {
                int j = n0w + ni * 8 + tg * 2;
                float d0 = fmaxf(si + sqj[j]     - 2.f * C[mi][ni][e2 * 2],     0.f);
                float d1 = fmaxf(si + sqj[j + 1] - 2.f * C[mi][ni][e2 * 2 + 1], 0.f);
                __half h0 = __float2half_rn(d0), h1 = __float2half_rn(d1);
                *(__half*)(stage + j * 256 + ((i * 2) ^ ((j & 7) << 4)))             = h0;
                *(__half*)(stage + (j + 1) * 256 + ((i * 2) ^ (((j + 1) & 7) << 4))) = h1;
            }
        }
    __syncthreads();
    #pragma unroll
    for (int m = 0; m < 8; m++) {
        int fi = t + 256 * m;
        int row = fi >> 4, c16 = fi & 15;
        uint4 v = *(uint4*)(stage + row * 256 + ((c16 * 16) ^ ((row & 7) << 4)));
        *(uint4*)&g_D2h[(size_t)(j0 + row) * n + i0 + c16 * 8] = v;
    }
}

// ---------------- K: alpha — mu_num = W1 @ x (1 term), S1 sums ----------------
// dyn smem: Wh 0 (16K), xh 16384 (8K) -> 24576 ; grid (n/128, 32), 2 chunks/block
__global__ void __launch_bounds__(256) k_alpha(const float* __restrict__ pr0, int n) {
    extern __shared__ char smc[];
    uint32_t sb = su32(smc);
    const int t = threadIdx.x, w = t >> 5, lane = t & 31;
    const int j0 = blockIdx.x * 128;
    const int ibase0 = blockIdx.y * 128;
    const float r0v = fminf(*pr0, sqrtf(__uint_as_float(g_maxbits)));
    const float R2i = 1.0f / (r0v * r0v);

    float C[8][4];
    #pragma unroll
    for (int b = 0; b < 8; b++)
        #pragma unroll
        for (int e = 0; e < 4; e++) C[b][e] = 0.f;

    #pragma unroll
    for (int ch = 0; ch < 2; ch++) {
        int ib = ibase0 + ch * 64;
        if (ch) __syncthreads();
        for (int q = t; q < 512; q += 256) {
            int row = q >> 3, cb = (q & 7) * 16;
            *(uint4*)(smc + 16384 + SWZ(row * 128 + cb)) =
                *(const uint4*)&g_xh[(size_t)(ib + row) * P + cb / 2];
        }
        {
            int j = t >> 1, ih = (t & 1) * 32;
            const __half* drow = &g_D2h[(size_t)(j0 + j) * n + ib + ih];
            float s = 0.f;
            #pragma unroll
            for (int q = 0; q < 4; q++) {
                uint4 dv4 = *(const uint4*)&drow[q * 8];
                uint32_t din[4] = {dv4.x, dv4.y, dv4.z, dv4.w};
                uint32_t hh[4];
                #pragma unroll
                for (int k = 0; k < 4; k++) {
                    float2 d2f = __half22float2(*(__half2*)&din[k]);
                    float w0 = w1f(d2f.x, R2i), w1v = w1f(d2f.y, R2i);
                    s += w0 + w1v;
                    hh[k] = packh2(w0, w1v);
                }
                *(uint4*)(smc + SWZ(j * 128 + (ih + q * 8) * 2)) = *(uint4*)hh;
            }
            s += __shfl_xor_sync(0xffffffffu, s, 1);
            if ((t & 1) == 0) atomicAdd(&g_S1[j0 + j], s);
        }
        __syncthreads();
        #pragma unroll
        for (int ks = 0; ks < 4; ks++) {
            int k0 = ks * 16;
            uint32_t Awh[4];
            ldm_x4(Awh, frag_addr(sb, lane, w * 16, k0));
            #pragma unroll
            for (int gq = 0; gq < 4; gq++) {
                uint32_t Bh[4];
                ldm_x4t(Bh, frag_addr(sb + 16384, lane, k0, gq * 16));
                #pragma unroll
                for (int h = 0; h < 2; h++) {
                    uint32_t bh[2] = {Bh[h * 2], Bh[h * 2 + 1]};
                    mma16816(C[gq * 2 + h], Awh, bh);
                }
            }
        }
    }
    const int g = lane >> 2, tg = lane & 3;
    #pragma unroll
    for (int ni = 0; ni < 8; ni++)
        #pragma unroll
        for (int e = 0; e < 4; e++) {
            int j = j0 + w * 16 + g + (e >> 1) * 8;
            int p = ni * 8 + tg * 2 + (e & 1);
            atomicAdd(&g_mun[(size_t)j * P + p], C[ni][e]);
        }
}

// ---------------- K: U = x - mu (+ splits), bU, sqrt(||U||^2) + zero-init (S2, accZ) ----------------
__global__ void k_U(const float* __restrict__ x, int n) {
    int gt = blockIdx.x * blockDim.x + threadIdx.x;
    int w = gt >> 5;
    int lane = threadIdx.x & 31;
    *(float2*)&g_accZ[(size_t)gt * 2] = make_float2(0.f, 0.f);
    if (gt < n) g_S2[gt] = 0.f;
    if (w >= n) return;
    float S1 = g_S1[w];
    float b = 0.f, un2 = 0.f;
    #pragma unroll
    for (int h = 0; h < 2; h++) {
        int p = lane + 32 * h;
        float mu = g_mun[(size_t)w * P + p] / S1;
        float xv = x[(size_t)w * P + p];
        if (isnan(mu)) mu = xv;
        float U = xv - mu;
        __half uh = __float2half_rn(U);
        g_Uh[(size_t)w * P + p] = uh;
        g_Ul[(size_t)w * P + p] = __float2half_rn(U - __half2float(uh));
        b += xv * U;
        un2 += U * U;
    }
    #pragma unroll
    for (int o = 16; o; o >>= 1) {
        b += __shfl_xor_sync(0xffffffffu, b, o);
        un2 += __shfl_xor_sync(0xffffffffu, un2, o);
    }
    if (lane == 0) { g_bU[w] = b; g_sU2[w] = sqrtf(un2); }
}

// ---------------- K: beta — c-GEMM(x3) + weights + acc-GEMM(x1) ----------------
// dyn smem: Wh 0 (16K), Dst 16384 (16K), xh 32768 (8K), xl 40960 (8K),
//           bU 49152(512), su2 49664(512) -> 50176 ; grid (n/128, 16), 4 chunks
__global__ void __launch_bounds__(256) k_beta(const float* __restrict__ pr1,
                                              const float* __restrict__ pr2, int n) {
    extern __shared__ char smc[];
    uint32_t sb = su32(smc);
    float* bUs  = (float*)(smc + 49152);
    float* su2s = (float*)(smc + 49664);
    const int t = threadIdx.x, w = t >> 5, lane = t & 31;
    const int j0 = blockIdx.x * 128;
    const int ibase0 = blockIdx.y * 256;
    const float md = sqrtf(__uint_as_float(g_maxbits));
    const float rr1 = fminf(*pr1, md), rr2 = fminf(*pr2, md);
    const float a1 = 2.0f / rr1, a2 = 2.0f / rr2;
    const int g = lane >> 2, tg = lane & 3;

    for (int q = t; q < 1024; q += 256) {
        int row = q >> 3, cb = (q & 7) * 16;
        uint32_t off = SWZ(row * 128 + cb);
        *(uint4*)(smc + off)         = *(const uint4*)&g_Uh[(size_t)(j0 + row) * P + cb / 2];
        *(uint4*)(smc + 16384 + off) = *(const uint4*)&g_Ul[(size_t)(j0 + row) * P + cb / 2];
    }
    if (t < 128) { bUs[t] = g_bU[j0 + t]; su2s[t] = g_sU2[j0 + t]; }
    __syncthreads();
    uint32_t AUh[4][4], AUl[4][4];
    #pragma unroll
    for (int ks = 0; ks < 4; ks++) {
        ldm_x4(AUh[ks], frag_addr(sb,         lane, w * 16, ks * 16));
        ldm_x4(AUl[ks], frag_addr(sb + 16384, lane, w * 16, ks * 16));
    }
    __syncthreads();

    float accC[8][4];
    #pragma unroll
    for (int b = 0; b < 8; b++)
        #pragma unroll
        for (int e = 0; e < 4; e++) accC[b][e] = 0.f;

    #pragma unroll 1
    for (int ch = 0; ch < 4; ch++) {
        int ib = ibase0 + ch * 64;
        if (ch) __syncthreads();
        for (int q = t; q < 512; q += 256) {
            int row = q >> 3, cb = (q & 7) * 16;
            uint32_t off = SWZ(row * 128 + cb);
            *(uint4*)(smc + 32768 + off) = *(const uint4*)&g_xh[(size_t)(ib + row) * P + cb / 2];
            *(uint4*)(smc + 40960 + off) = *(const uint4*)&g_xl[(size_t)(ib + row) * P + cb / 2];
        }
        for (int q = t; q < 1024; q += 256) {
            int j = q >> 3, c = q & 7;
            *(uint4*)(smc + 16384 + j * 128 + ((c * 16) ^ ((j & 7) << 4))) =
                *(const uint4*)&g_D2h[(size_t)(j0 + j) * n + ib + c * 8];
        }
        __syncthreads();
        float cC[8][4];
        #pragma unroll
        for (int b = 0; b < 8; b++)
            #pragma unroll
            for (int e = 0; e < 4; e++) cC[b][e] = 0.f;
        #pragma unroll
        for (int ks = 0; ks < 4; ks++) {
            int k0 = ks * 16;
            #pragma unroll
            for (int gq = 0; gq < 4; gq++) {
                uint32_t Bh[4], Bl[4];
                ldm_x4(Bh, frag_addr(sb + 32768, lane, gq * 16, k0));
                ldm_x4(Bl, frag_addr(sb + 40960, lane, gq * 16, k0));
                #pragma unroll
                for (int h = 0; h < 2; h++) {
                    int ni = gq * 2 + h;
                    uint32_t bh[2] = {Bh[h], Bh[h + 2]};
                    uint32_t bl[2] = {Bl[h], Bl[h + 2]};
                    mma16816(cC[ni], AUh[ks], bh);
                    mma16816(cC[ni], AUh[ks], bl);
                    mma16816(cC[ni], AUl[ks], bh);
                }
            }
        }
        #pragma unroll
        for (int e2 = 0; e2 < 2; e2++) {
            int jl = w * 16 + g + e2 * 8;
            float bj = bUs[jl], su2 = su2s[jl];
            float rs = 0.f;
            #pragma unroll
            for (int ni = 0; ni < 8; ni++) {
                int il = ni * 8 + tg * 2;
                float2 dd = __half22float2(
                    *(__half2*)(smc + 16384 + jl * 128 + ((il * 2) ^ ((jl & 7) << 4))));
                float wv[2], d2v[2] = {dd.x, dd.y};
                #pragma unroll
                for (int q = 0; q < 2; q++) {
                    float cp = cC[ni][e2 * 2 + q] - bj;
                    float du = fmaxf(fabsf(cp) * su2, 1e-3f);
                    float dv = asqrt(fmaxf(d2v[q] - du * du, 1e-6f));
                    wv[q] = w2f(dv, a1) * w2f(du, a2);
                }
                rs += wv[0] + wv[1];
                *(uint32_t*)(smc + SWZ(jl * 128 + il * 2)) = packh2(wv[0], wv[1]);
            }
            rs += __shfl_xor_sync(0xffffffffu, rs, 1);
            rs += __shfl_xor_sync(0xffffffffu, rs, 2);
            if (tg == 0) atomicAdd(&g_S2[j0 + jl], rs);
        }
        __syncthreads();
        #pragma unroll
        for (int ks = 0; ks < 4; ks++) {
            int k0 = ks * 16;
            uint32_t Awh[4];
            ldm_x4(Awh, frag_addr(sb, lane, w * 16, k0));
            #pragma unroll
            for (int gq = 0; gq < 4; gq++) {
                uint32_t Bh[4];
                ldm_x4t(Bh, frag_addr(sb + 32768, lane, k0, gq * 16));
                #pragma unroll
                for (int h = 0; h < 2; h++) {
                    uint32_t bh[2] = {Bh[h * 2], Bh[h * 2 + 1]};
                    mma16816(accC[gq * 2 + h], Awh, bh);
                }
            }
        }
    }
    #pragma unroll
    for (int ni = 0; ni < 8; ni++)
        #pragma unroll
        for (int e = 0; e < 4; e++) {
            int j = j0 + w * 16 + g + (e >> 1) * 8;
            int p = ni * 8 + tg * 2 + (e & 1);
            atomicAdd(&g_accZ[(size_t)j * P + p], accC[ni][e]);
        }
}

// ---------------- K: output ----------------
__global__ void k_out(const float* __restrict__ x, float* __restrict__ out, int n) {
    int idx = blockIdx.x * blockDim.x + threadIdx.x;
    if (idx >= n * P) return;
    int j = idx >> 6;
    float e = g_accZ[idx] / g_S2[j];
    if (isnan(e)) e = x[idx];
    out[idx] = e;
}

extern "C" void kernel_launch(void* const* d_in, const int* in_sizes, int n_in,
                              void* d_out, int out_size) {
    const float* x  = (const float*)d_in[0];
    const float* r0 = (const float*)d_in[1];
    const float* r1 = (const float*)d_in[2];
    const float* r2 = (const float*)d_in[3];
    float* out = (float*)d_out;
    const int n = in_sizes[0] / P;  // 4096
    const int nb = n / 128;

    k_prep<<<(n + 7) / 8, 256>>>(x, n);

    cudaFuncSetAttribute(k_gram, cudaFuncAttributeMaxDynamicSharedMemorySize, 50176);
    k_gram<<<nb * (nb + 1) / 2, 256, 50176>>>(n);

    cudaFuncSetAttribute(k_alpha, cudaFuncAttributeMaxDynamicSharedMemorySize, 24576);
    k_alpha<<<dim3(nb, 32), 256, 24576>>>(r0, n);

    k_U<<<(n + 7) / 8, 256>>>(x, n);

    cudaFuncSetAttribute(k_beta, cudaFuncAttributeMaxDynamicSharedMemorySize, 50176);
    k_beta<<<dim3(nb, 16), 256, 50176>>>(r1, r2, n);

    k_out<<<(n * P + 255) / 256, 256>>>(x, out, n);
}

// round 8
// speedup vs baseline: 2.8562x; 1.2272x over previous
#include <cuda_runtime.h>
#include <cuda_fp16.h>
#include <math.h>
#include <stdint.h>

#define P 64
#define NMAX 4096

// ---------------- persistent device scratch ----------------
__device__ float g_sq[NMAX];
__device__ __half g_D2h[(size_t)NMAX * NMAX];
__device__ unsigned int g_maxbits;
__device__ float g_S1[NMAX];
__device__ float g_mun[NMAX * P];
__device__ float g_bU[NMAX];
__device__ float g_sU2[NMAX];
__device__ float g_S2[NMAX];
__device__ float g_accZ[NMAX * P];
__device__ __half g_xh[NMAX * P], g_xl[NMAX * P];
__device__ __half g_Uh[NMAX * P], g_Ul[NMAX * P];

// ---------------- helpers ----------------
__device__ __forceinline__ uint32_t su32(const void* p) {
    uint32_t a;
    asm("{ .reg .u64 t; cvta.to.shared.u64 t, %1; cvt.u32.u64 %0, t; }" : "=r"(a) : "l"(p));
    return a;
}
#define SWZ(b) ((uint32_t)(b) ^ ((((uint32_t)(b)) >> 3) & 0x70))

__device__ __forceinline__ uint32_t frag_addr(uint32_t base, int lane, int row0, int col0) {
    int r = row0 + (lane & 7) + ((lane >> 3) & 1) * 8;
    int cb = (col0 + (lane >> 4) * 8) * 2;
    return base + SWZ(r * 128 + cb);
}
__device__ __forceinline__ void ldm_x4(uint32_t* r, uint32_t a) {
    asm volatile("ldmatrix.sync.aligned.m8n8.x4.shared.b16 {%0,%1,%2,%3}, [%4];"
                 : "=r"(r[0]), "=r"(r[1]), "=r"(r[2]), "=r"(r[3]) : "r"(a));
}
__device__ __forceinline__ void ldm_x4t(uint32_t* r, uint32_t a) {
    asm volatile("ldmatrix.sync.aligned.m8n8.x4.trans.shared.b16 {%0,%1,%2,%3}, [%4];"
                 : "=r"(r[0]), "=r"(r[1]), "=r"(r[2]), "=r"(r[3]) : "r"(a));
}
__device__ __forceinline__ void mma16816(float* c, const uint32_t* a, const uint32_t* b) {
    asm volatile(
        "mma.sync.aligned.m16n8k16.row.col.f32.f16.f16.f32 "
        "{%0,%1,%2,%3}, {%4,%5,%6,%7}, {%8,%9}, {%0,%1,%2,%3};"
        : "+f"(c[0]), "+f"(c[1]), "+f"(c[2]), "+f"(c[3])
        : "r"(a[0]), "r"(a[1]), "r"(a[2]), "r"(a[3]), "r"(b[0]), "r"(b[1]));
}
__device__ __forceinline__ uint32_t packh2(float a, float b) {
    __half2 h = __floats2half2_rn(a, b);
    return *(uint32_t*)&h;
}
__device__ __forceinline__ float asqrt(float x) { float r; asm("sqrt.approx.f32 %0,%1;" : "=f"(r) : "f"(x)); return r; }
__device__ __forceinline__ float w1f(float d2, float R2i) {
    float s = fmaxf(fmaf(-d2, R2i, 1.0f), 0.0f);
    return s * s * s;
}
__device__ __forceinline__ float w2f(float d, float a) {
    float t = __saturatef(fmaf(d, a, -1.0f));
    float s = fmaf(-t, t, 1.0f);
    return s * s * s;
}

// ---------------- K: prep — sq norms + fp16 split + zero-init ----------------
__global__ void k_prep(const float* __restrict__ x, int n) {
    int gt = blockIdx.x * blockDim.x + threadIdx.x;
    int w = gt >> 5;
    int lane = threadIdx.x & 31;
    *(float2*)&g_mun[(size_t)gt * 2] = make_float2(0.f, 0.f);
    if (gt < n) g_S1[gt] = 0.f;
    if (gt == 0) g_maxbits = 0u;
    if (w >= n) return;
    float v0 = x[(size_t)w * P + lane], v1 = x[(size_t)w * P + 32 + lane];
    __half h0 = __float2half_rn(v0), h1 = __float2half_rn(v1);
    g_xh[(size_t)w * P + lane] = h0;
    g_xh[(size_t)w * P + 32 + lane] = h1;
    g_xl[(size_t)w * P + lane] = __float2half_rn(v0 - __half2float(h0));
    g_xl[(size_t)w * P + 32 + lane] = __float2half_rn(v1 - __half2float(h1));
    float s = v0 * v0 + v1 * v1;
    #pragma unroll
    for (int o = 16; o; o >>= 1) s += __shfl_xor_sync(0xffffffffu, s, o);
    if (lane == 0) g_sq[w] = s;
}

// ---------------- K: gram (upper-triangle) -> D2h, mirror store ----------------
__global__ void __launch_bounds__(256) k_gram(int n) {
    extern __shared__ char smc[];
    __shared__ float wmax[8];
    uint32_t sb = su32(smc);
    const int t = threadIdx.x, w = t >> 5, lane = t & 31;
    const int nb = n >> 7;
    int k = blockIdx.x, a = 0;
    while (k >= nb - a) { k -= nb - a; a++; }
    const int ti = a, tj = a + k;
    const int i0 = ti * 128, j0 = tj * 128;
    float* sqi = (float*)(smc + 49152);
    float* sqj = (float*)(smc + 49664);
    char* stage = smc + 16384;

    for (int q = t; q < 1024; q += 256) {
        int row = q >> 3, cb = (q & 7) * 16;
        uint32_t off = SWZ(row * 128 + cb);
        *(uint4*)(smc + off)         = *(const uint4*)&g_xh[(size_t)(i0 + row) * P + cb / 2];
        *(uint4*)(smc + 16384 + off) = *(const uint4*)&g_xh[(size_t)(j0 + row) * P + cb / 2];
        *(uint4*)(smc + 32768 + off) = *(const uint4*)&g_xl[(size_t)(j0 + row) * P + cb / 2];
    }
    if (t < 128) sqi[t] = g_sq[i0 + t];
    else sqj[t - 128] = g_sq[j0 + t - 128];
    __syncthreads();

    const int m0 = (w & 3) * 32, n0w = (w >> 2) * 64;
    float C[2][8][4];
    #pragma unroll
    for (int a2 = 0; a2 < 2; a2++)
        #pragma unroll
        for (int b = 0; b < 8; b++)
            #pragma unroll
            for (int e = 0; e < 4; e++) C[a2][b][e] = 0.f;

    #pragma unroll
    for (int ks = 0; ks < 4; ks++) {
        int k0 = ks * 16;
        uint32_t Ah[2][4];
        #pragma unroll
        for (int mi = 0; mi < 2; mi++)
            ldm_x4(Ah[mi], frag_addr(sb, lane, m0 + mi * 16, k0));
        #pragma unroll
        for (int gq = 0; gq < 4; gq++) {
            uint32_t Bh[4], Bl[4];
            ldm_x4(Bh, frag_addr(sb + 16384, lane, n0w + gq * 16, k0));
            ldm_x4(Bl, frag_addr(sb + 32768, lane, n0w + gq * 16, k0));
            #pragma unroll
            for (int h = 0; h < 2; h++) {
                int ni = gq * 2 + h;
                uint32_t bh[2] = {Bh[h], Bh[h + 2]};
                uint32_t bl[2] = {Bl[h], Bl[h + 2]};
                #pragma unroll
                for (int mi = 0; mi < 2; mi++) {
                    mma16816(C[mi][ni], Ah[mi], bh);
                    mma16816(C[mi][ni], Ah[mi], bl);
                }
            }
        }
    }
    __syncthreads();

    const int g = lane >> 2, tg = lane & 3;
    float lmax = 0.f;
    #pragma unroll
    for (int mi = 0; mi < 2; mi++)
        #pragma unroll
        for (int e2 = 0; e2 < 2; e2++) {
            int i = m0 + mi * 16 + g + e2 * 8;
            float si = sqi[i];
            #pragma unroll
            for (int ni = 0; ni < 8; ni++) {
                int j = n0w + ni * 8 + tg * 2;
                float d0 = fmaxf(si + sqj[j]     - 2.f * C[mi][ni][e2 * 2],     0.f);
                float d1 = fmaxf(si + sqj[j + 1] - 2.f * C[mi][ni][e2 * 2 + 1], 0.f);
                lmax = fmaxf(lmax, fmaxf(d0, d1));
                *(uint32_t*)(stage + i * 256 + ((j * 2) ^ ((i & 7) << 4))) = packh2(d0, d1);
            }
        }
    #pragma unroll
    for (int o = 16; o; o >>= 1) lmax = fmaxf(lmax, __shfl_xor_sync(0xffffffffu, lmax, o));
    if (lane == 0) wmax[w] = lmax;
    __syncthreads();
    if (t == 0) {
        float m = wmax[0];
        #pragma unroll
        for (int q = 1; q < 8; q++) m = fmaxf(m, wmax[q]);
        atomicMax(&g_maxbits, __float_as_uint(m));
    }
    #pragma unroll
    for (int m = 0; m < 8; m++) {
        int fi = t + 256 * m;
        int row = fi >> 4, c16 = fi & 15;
        uint4 v = *(uint4*)(stage + row * 256 + ((c16 * 16) ^ ((row & 7) << 4)));
        *(uint4*)&g_D2h[(size_t)(i0 + row) * n + j0 + c16 * 8] = v;
    }

    if (ti == tj) return;

    __syncthreads();
    #pragma unroll
    for (int mi = 0; mi < 2; mi++)
        #pragma unroll
        for (int e2 = 0; e2 < 2; e2++) {
            int i = m0 + mi * 16 + g + e2 * 8;
            float si = sqi[i];
            #pragma unroll
            for (int ni = 0; ni < 8; ni++) {
                int j = n0w + ni * 8 + tg * 2;
                float d0 = fmaxf(si + sqj[j]     - 2.f * C[mi][ni][e2 * 2],     0.f);
                float d1 = fmaxf(si + sqj[j + 1] - 2.f * C[mi][ni][e2 * 2 + 1], 0.f);
                __half h0 = __float2half_rn(d0), h1 = __float2half_rn(d1);
                *(__half*)(stage + j * 256 + ((i * 2) ^ ((j & 7) << 4)))             = h0;
                *(__half*)(stage + (j + 1) * 256 + ((i * 2) ^ (((j + 1) & 7) << 4))) = h1;
            }
        }
    __syncthreads();
    #pragma unroll
    for (int m = 0; m < 8; m++) {
        int fi = t + 256 * m;
        int row = fi >> 4, c16 = fi & 15;
        uint4 v = *(uint4*)(stage + row * 256 + ((c16 * 16) ^ ((row & 7) << 4)));
        *(uint4*)&g_D2h[(size_t)(j0 + row) * n + i0 + c16 * 8] = v;
    }
}

// ---------------- K: alpha — pipelined (register prefetch) ----------------
// dyn smem: Wh 0 (16K), xh 16384 (8K) -> 24576 ; grid (n/128, 32), 2 chunks
__global__ void __launch_bounds__(256) k_alpha(const float* __restrict__ pr0, int n) {
    extern __shared__ char smc[];
    uint32_t sb = su32(smc);
    const int t = threadIdx.x, w = t >> 5, lane = t & 31;
    const int j0 = blockIdx.x * 128;
    const int ibase0 = blockIdx.y * 128;
    const float r0v = fminf(*pr0, sqrtf(__uint_as_float(g_maxbits)));
    const float R2i = 1.0f / (r0v * r0v);
    const int xrow = t >> 3, xcb = (t & 7) * 16;        // x-tile LDG coords (2 iters)
    const int wj = t >> 1, wih = (t & 1) * 32;          // weight-gen coords

    float C[8][4];
    #pragma unroll
    for (int b = 0; b < 8; b++)
        #pragma unroll
        for (int e = 0; e < 4; e++) C[b][e] = 0.f;

    uint4 px[2], pd[4];
    #define A_LD(ib) do { \
        px[0] = *(const uint4*)&g_xh[(size_t)((ib) + xrow) * P + xcb / 2]; \
        px[1] = *(const uint4*)&g_xh[(size_t)((ib) + 32 + xrow) * P + xcb / 2]; \
        const __half* _dr = &g_D2h[(size_t)(j0 + wj) * n + (ib) + wih]; \
        pd[0] = *(const uint4*)&_dr[0];  pd[1] = *(const uint4*)&_dr[8]; \
        pd[2] = *(const uint4*)&_dr[16]; pd[3] = *(const uint4*)&_dr[24]; \
    } while (0)

    A_LD(ibase0);
    #pragma unroll
    for (int ch = 0; ch < 2; ch++) {
        if (ch) __syncthreads();
        *(uint4*)(smc + 16384 + SWZ(xrow * 128 + xcb))        = px[0];
        *(uint4*)(smc + 16384 + SWZ((32 + xrow) * 128 + xcb)) = px[1];
        // weight-gen from registers
        {
            float s = 0.f;
            #pragma unroll
            for (int q = 0; q < 4; q++) {
                uint32_t din[4] = {pd[q].x, pd[q].y, pd[q].z, pd[q].w};
                uint32_t hh[4];
                #pragma unroll
                for (int k = 0; k < 4; k++) {
                    float2 d2f = __half22float2(*(__half2*)&din[k]);
                    float w0 = w1f(d2f.x, R2i), w1v = w1f(d2f.y, R2i);
                    s += w0 + w1v;
                    hh[k] = packh2(w0, w1v);
                }
                *(uint4*)(smc + SWZ(wj * 128 + (wih + q * 8) * 2)) = *(uint4*)hh;
            }
            s += __shfl_xor_sync(0xffffffffu, s, 1);
            if ((t & 1) == 0) atomicAdd(&g_S1[j0 + wj], s);
        }
        if (ch == 0) A_LD(ibase0 + 64);   // overlap next chunk's LDGs with MMA
        __syncthreads();
        #pragma unroll
        for (int ks = 0; ks < 4; ks++) {
            int k0 = ks * 16;
            uint32_t Awh[4];
            ldm_x4(Awh, frag_addr(sb, lane, w * 16, k0));
            #pragma unroll
            for (int gq = 0; gq < 4; gq++) {
                uint32_t Bh[4];
                ldm_x4t(Bh, frag_addr(sb + 16384, lane, k0, gq * 16));
                #pragma unroll
                for (int h = 0; h < 2; h++) {
                    uint32_t bh[2] = {Bh[h * 2], Bh[h * 2 + 1]};
                    mma16816(C[gq * 2 + h], Awh, bh);
                }
            }
        }
    }
    const int g = lane >> 2, tg = lane & 3;
    #pragma unroll
    for (int ni = 0; ni < 8; ni++)
        #pragma unroll
        for (int e = 0; e < 4; e++) {
            int j = j0 + w * 16 + g + (e >> 1) * 8;
            int p = ni * 8 + tg * 2 + (e & 1);
            atomicAdd(&g_mun[(size_t)j * P + p], C[ni][e]);
        }
}

// ---------------- K: U = x - mu (+ splits), bU, sqrt(||U||^2), zero-init ----------------
__global__ void k_U(const float* __restrict__ x, int n) {
    int gt = blockIdx.x * blockDim.x + threadIdx.x;
    int w = gt >> 5;
    int lane = threadIdx.x & 31;
    *(float2*)&g_accZ[(size_t)gt * 2] = make_float2(0.f, 0.f);
    if (gt < n) g_S2[gt] = 0.f;
    if (w >= n) return;
    float S1 = g_S1[w];
    float b = 0.f, un2 = 0.f;
    #pragma unroll
    for (int h = 0; h < 2; h++) {
        int p = lane + 32 * h;
        float mu = g_mun[(size_t)w * P + p] / S1;
        float xv = x[(size_t)w * P + p];
        if (isnan(mu)) mu = xv;
        float U = xv - mu;
        __half uh = __float2half_rn(U);
        g_Uh[(size_t)w * P + p] = uh;
        g_Ul[(size_t)w * P + p] = __float2half_rn(U - __half2float(uh));
        b += xv * U;
        un2 += U * U;
    }
    #pragma unroll
    for (int o = 16; o; o >>= 1) {
        b += __shfl_xor_sync(0xffffffffu, b, o);
        un2 += __shfl_xor_sync(0xffffffffu, un2, o);
    }
    if (lane == 0) { g_bU[w] = b; g_sU2[w] = sqrtf(un2); }
}

// ---------------- K: beta — pipelined c-GEMM(x3) + weights + acc-GEMM(x1) ----------------
// dyn smem: Wh 0 (16K), Dst 16384 (16K), xh 32768 (8K), xl 40960 (8K),
//           bU 49152(512), su2 49664(512) -> 50176 ; grid (n/128, 16), 4 chunks
__global__ void __launch_bounds__(256, 2) k_beta(const float* __restrict__ pr1,
                                                 const float* __restrict__ pr2, int n) {
    extern __shared__ char smc[];
    uint32_t sb = su32(smc);
    float* bUs  = (float*)(smc + 49152);
    float* su2s = (float*)(smc + 49664);
    const int t = threadIdx.x, w = t >> 5, lane = t & 31;
    const int j0 = blockIdx.x * 128;
    const int ibase0 = blockIdx.y * 256;
    const float md = sqrtf(__uint_as_float(g_maxbits));
    const float rr1 = fminf(*pr1, md), rr2 = fminf(*pr2, md);
    const float a1 = 2.0f / rr1, a2 = 2.0f / rr2;
    const int g = lane >> 2, tg = lane & 3;
    const int xrow = t >> 3, xcb = (t & 7) * 16;
    const int drj = t >> 3, drc = t & 7;

    for (int q = t; q < 1024; q += 256) {
        int row = q >> 3, cb = (q & 7) * 16;
        uint32_t off = SWZ(row * 128 + cb);
        *(uint4*)(smc + off)         = *(const uint4*)&g_Uh[(size_t)(j0 + row) * P + cb / 2];
        *(uint4*)(smc + 16384 + off) = *(const uint4*)&g_Ul[(size_t)(j0 + row) * P + cb / 2];
    }
    if (t < 128) { bUs[t] = g_bU[j0 + t]; su2s[t] = g_sU2[j0 + t]; }
    __syncthreads();
    uint32_t AUh[4][4], AUl[4][4];
    #pragma unroll
    for (int ks = 0; ks < 4; ks++) {
        ldm_x4(AUh[ks], frag_addr(sb,         lane, w * 16, ks * 16));
        ldm_x4(AUl[ks], frag_addr(sb + 16384, lane, w * 16, ks * 16));
    }
    __syncthreads();

    float accC[8][4];
    #pragma unroll
    for (int b = 0; b < 8; b++)
        #pragma unroll
        for (int e = 0; e < 4; e++) accC[b][e] = 0.f;

    uint4 pxh[2], pxl[2], pdq[4];
    #define B_LD(ib) do { \
        pxh[0] = *(const uint4*)&g_xh[(size_t)((ib) + xrow) * P + xcb / 2]; \
        pxl[0] = *(const uint4*)&g_xl[(size_t)((ib) + xrow) * P + xcb / 2]; \
        pxh[1] = *(const uint4*)&g_xh[(size_t)((ib) + 32 + xrow) * P + xcb / 2]; \
        pxl[1] = *(const uint4*)&g_xl[(size_t)((ib) + 32 + xrow) * P + xcb / 2]; \
        pdq[0] = *(const uint4*)&g_D2h[(size_t)(j0 + drj) * n + (ib) + drc * 8]; \
        pdq[1] = *(const uint4*)&g_D2h[(size_t)(j0 + 32 + drj) * n + (ib) + drc * 8]; \
        pdq[2] = *(const uint4*)&g_D2h[(size_t)(j0 + 64 + drj) * n + (ib) + drc * 8]; \
        pdq[3] = *(const uint4*)&g_D2h[(size_t)(j0 + 96 + drj) * n + (ib) + drc * 8]; \
    } while (0)

    B_LD(ibase0);
    #pragma unroll 1
    for (int ch = 0; ch < 4; ch++) {
        int ib = ibase0 + ch * 64;
        if (ch) __syncthreads();
        // store prefetched chunk to smem
        {
            uint32_t off0 = SWZ(xrow * 128 + xcb);
            uint32_t off1 = SWZ((32 + xrow) * 128 + xcb);
            *(uint4*)(smc + 32768 + off0) = pxh[0];
            *(uint4*)(smc + 40960 + off0) = pxl[0];
            *(uint4*)(smc + 32768 + off1) = pxh[1];
            *(uint4*)(smc + 40960 + off1) = pxl[1];
            #pragma unroll
            for (int m = 0; m < 4; m++) {
                int j = drj + 32 * m;
                *(uint4*)(smc + 16384 + j * 128 + ((drc * 16) ^ ((j & 7) << 4))) = pdq[m];
            }
        }
        if (ch < 3) B_LD(ib + 64);   // overlap next chunk's LDGs with this chunk's compute
        __syncthreads();
        float cC[8][4];
        #pragma unroll
        for (int b = 0; b < 8; b++)
            #pragma unroll
            for (int e = 0; e < 4; e++) cC[b][e] = 0.f;
        #pragma unroll
        for (int ks = 0; ks < 4; ks++) {
            int k0 = ks * 16;
            #pragma unroll
            for (int gq = 0; gq < 4; gq++) {
                uint32_t Bh[4], Bl[4];
                ldm_x4(Bh, frag_addr(sb + 32768, lane, gq * 16, k0));
                ldm_x4(Bl, frag_addr(sb + 40960, lane, gq * 16, k0));
                #pragma unroll
                for (int h = 0; h < 2; h++) {
                    int ni = gq * 2 + h;
                    uint32_t bh[2] = {Bh[h], Bh[h + 2]};
                    uint32_t bl[2] = {Bl[h], Bl[h + 2]};
                    mma16816(cC[ni], AUh[ks], bh);
                    mma16816(cC[ni], AUh[ks], bl);
                    mma16816(cC[ni], AUl[ks], bh);
                }
            }
        }
        #pragma unroll
        for (int e2 = 0; e2 < 2; e2++) {
            int jl = w * 16 + g + e2 * 8;
            float bj = bUs[jl], su2 = su2s[jl];
            float rs = 0.f;
            #pragma unroll
            for (int ni = 0; ni < 8; ni++) {
                int il = ni * 8 + tg * 2;
                float2 dd = __half22float2(
                    *(__half2*)(smc + 16384 + jl * 128 + ((il * 2) ^ ((jl & 7) << 4))));
                float wv[2], d2v[2] = {dd.x, dd.y};
                #pragma unroll
                for (int q = 0; q < 2; q++) {
                    float cp = cC[ni][e2 * 2 + q] - bj;
                    float du = fmaxf(fabsf(cp) * su2, 1e-3f);
                    float dv = asqrt(fmaxf(d2v[q] - du * du, 1e-6f));
                    wv[q] = w2f(dv, a1) * w2f(du, a2);
                }
                rs += wv[0] + wv[1];
                *(uint32_t*)(smc + SWZ(jl * 128 + il * 2)) = packh2(wv[0], wv[1]);
            }
            rs += __shfl_xor_sync(0xffffffffu, rs, 1);
            rs += __shfl_xor_sync(0xffffffffu, rs, 2);
            if (tg == 0) atomicAdd(&g_S2[j0 + jl], rs);
        }
        __syncthreads();
        #pragma unroll
        for (int ks = 0; ks < 4; ks++) {
            int k0 = ks * 16;
            uint32_t Awh[4];
            ldm_x4(Awh, frag_addr(sb, lane, w * 16, k0));
            #pragma unroll
            for (int gq = 0; gq < 4; gq++) {
                uint32_t Bh[4];
                ldm_x4t(Bh, frag_addr(sb + 32768, lane, k0, gq * 16));
                #pragma unroll
                for (int h = 0; h < 2; h++) {
                    uint32_t bh[2] = {Bh[h * 2], Bh[h * 2 + 1]};
                    mma16816(accC[gq * 2 + h], Awh, bh);
                }
            }
        }
    }
    #pragma unroll
    for (int ni = 0; ni < 8; ni++)
        #pragma unroll
        for (int e = 0; e < 4; e++) {
            int j = j0 + w * 16 + g + (e >> 1) * 8;
            int p = ni * 8 + tg * 2 + (e & 1);
            atomicAdd(&g_accZ[(size_t)j * P + p], accC[ni][e]);
        }
}

// ---------------- K: output ----------------
__global__ void k_out(const float* __restrict__ x, float* __restrict__ out, int n) {
    int idx = blockIdx.x * blockDim.x + threadIdx.x;
    if (idx >= n * P) return;
    int j = idx >> 6;
    float e = g_accZ[idx] / g_S2[j];
    if (isnan(e)) e = x[idx];
    out[idx] = e;
}

extern "C" void kernel_launch(void* const* d_in, const int* in_sizes, int n_in,
                              void* d_out, int out_size) {
    const float* x  = (const float*)d_in[0];
    const float* r0 = (const float*)d_in[1];
    const float* r1 = (const float*)d_in[2];
    const float* r2 = (const float*)d_in[3];
    float* out = (float*)d_out;
    const int n = in_sizes[0] / P;  // 4096
    const int nb = n / 128;

    k_prep<<<(n + 7) / 8, 256>>>(x, n);

    cudaFuncSetAttribute(k_gram, cudaFuncAttributeMaxDynamicSharedMemorySize, 50176);
    k_gram<<<nb * (nb + 1) / 2, 256, 50176>>>(n);

    cudaFuncSetAttribute(k_alpha, cudaFuncAttributeMaxDynamicSharedMemorySize, 24576);
    k_alpha<<<dim3(nb, 32), 256, 24576>>>(r0, n);

    k_U<<<(n + 7) / 8, 256>>>(x, n);

    cudaFuncSetAttribute(k_beta, cudaFuncAttributeMaxDynamicSharedMemorySize, 50176);
    k_beta<<<dim3(nb, 16), 256, 50176>>>(r1, r2, n);

    k_out<<<(n * P + 255) / 256, 256>>>(x, out, n);
}